// round 1
// baseline (speedup 1.0000x reference)
#include <cuda_runtime.h>

// Problem constants
#define BATCH    8
#define CHANNELS 512
#define HW       4096            // 64*64
#define HEADS    4
#define DHEAD    128             // CHANNELS/HEADS
#define NGROUPS  32
#define GSIZE    (CHANNELS / NGROUPS * HW)   // 16*4096 = 65536 (contiguous per (b,g))
#define EPS      1e-5f
#define QK_NCHUNK 8

// Scratch (device globals: allocation-free per harness rules)
__device__ float g_hn  [(size_t)BATCH * CHANNELS * HW];      // 64MB: normalized x; reused for attn@V output
__device__ float g_qkv [(size_t)BATCH * 3 * CHANNELS * HW];  // 201MB
__device__ float g_attn[(size_t)BATCH * HEADS * DHEAD * DHEAD]; // 2MB
__device__ float g_mean[BATCH * NGROUPS];
__device__ float g_rstd[BATCH * NGROUPS];

// ---------------------------------------------------------------------------
// GroupNorm stats: one block per (b, g); group data is contiguous 65536 floats
// ---------------------------------------------------------------------------
__global__ __launch_bounds__(256) void gn_stats(const float* __restrict__ x) {
    int bg = blockIdx.x;
    const float4* p = (const float4*)(x + (size_t)bg * GSIZE);
    float s = 0.f, sq = 0.f;
    for (int i = threadIdx.x; i < GSIZE / 4; i += 256) {
        float4 v = p[i];
        s  += v.x + v.y + v.z + v.w;
        sq += v.x * v.x + v.y * v.y + v.z * v.z + v.w * v.w;
    }
    __shared__ float ss[8], sr[8];
    #pragma unroll
    for (int o = 16; o; o >>= 1) {
        s  += __shfl_down_sync(~0u, s,  o);
        sq += __shfl_down_sync(~0u, sq, o);
    }
    int w = threadIdx.x >> 5, l = threadIdx.x & 31;
    if (l == 0) { ss[w] = s; sr[w] = sq; }
    __syncthreads();
    if (w == 0) {
        s  = (l < 8) ? ss[l] : 0.f;
        sq = (l < 8) ? sr[l] : 0.f;
        #pragma unroll
        for (int o = 4; o; o >>= 1) {
            s  += __shfl_down_sync(~0u, s,  o);
            sq += __shfl_down_sync(~0u, sq, o);
        }
        if (l == 0) {
            float m = s * (1.f / GSIZE);
            float v = sq * (1.f / GSIZE) - m * m;
            g_mean[bg] = m;
            g_rstd[bg] = rsqrtf(v + EPS);
        }
    }
}

// ---------------------------------------------------------------------------
// GroupNorm apply: hn = (x - mu)*rstd*gw + gb  (vectorized float4 elementwise)
// ---------------------------------------------------------------------------
__global__ __launch_bounds__(256) void gn_apply(const float* __restrict__ x,
                                                const float* __restrict__ gw,
                                                const float* __restrict__ gb) {
    size_t i = (size_t)blockIdx.x * 256 + threadIdx.x;   // float4 index
    size_t gidx = i * 4;
    int c  = (int)((gidx / HW) % CHANNELS);
    int bg = (int)(gidx / GSIZE);
    float r = g_rstd[bg];
    float w = gw[c] * r;
    float bb = gb[c] - g_mean[bg] * w;
    float4 v = ((const float4*)x)[i];
    v.x = v.x * w + bb; v.y = v.y * w + bb; v.z = v.z * w + bb; v.w = v.w * w + bb;
    ((float4*)g_hn)[i] = v;
}

// ---------------------------------------------------------------------------
// Generic fp32 SGEMM: C[z] = A[z] (MxK, row-major) * B[z] (KxN, row-major)
//                     (+ bias[M]) (+ residual)
// 128x128 tile, BK=16, 256 threads, 8x8 per-thread microtile.
// All dims divide the tiles exactly for every call site (no bounds checks).
// B batch offset is two-level: z -> (z / bInnerN)*bOuter + (z % bInnerN)*bInner
// ---------------------------------------------------------------------------
__global__ __launch_bounds__(256) void sgemm128(
    const float* __restrict__ A, const float* __restrict__ B, float* __restrict__ C,
    const float* __restrict__ bias, const float* __restrict__ R,
    int K, int N,
    long aStride,
    long bOuter, long bInner, int bInnerN,
    long cStride)
{
    __shared__ float As[16][132];   // transposed A tile (pad vs. STS conflicts)
    __shared__ float Bs[16][128];

    int z  = blockIdx.z;
    const float* Ab = A + (size_t)z * aStride;
    const float* Bb = B + (size_t)(z / bInnerN) * bOuter + (size_t)(z % bInnerN) * bInner;
    float*       Cb = C + (size_t)z * cStride;
    const float* Rb = R ? (R + (size_t)z * cStride) : nullptr;

    int m0 = blockIdx.y * 128, n0 = blockIdx.x * 128;
    int t  = threadIdx.x;
    int tx = t & 15, ty = t >> 4;

    int aRow0 = t >> 2, aC4 = t & 3;    // A tile: 128 rows x 16 cols = 512 float4
    int bRow0 = t >> 5, bC4 = t & 31;   // B tile: 16 rows x 128 cols = 512 float4

    float acc[8][8] = {};

    for (int k0 = 0; k0 < K; k0 += 16) {
        #pragma unroll
        for (int h = 0; h < 2; h++) {
            int row = aRow0 + h * 64;
            float4 v = *(const float4*)(Ab + (size_t)(m0 + row) * K + k0 + aC4 * 4);
            As[aC4 * 4 + 0][row] = v.x;
            As[aC4 * 4 + 1][row] = v.y;
            As[aC4 * 4 + 2][row] = v.z;
            As[aC4 * 4 + 3][row] = v.w;
        }
        #pragma unroll
        for (int h = 0; h < 2; h++) {
            int row = bRow0 + h * 8;
            *(float4*)(&Bs[row][bC4 * 4]) =
                *(const float4*)(Bb + (size_t)(k0 + row) * N + n0 + bC4 * 4);
        }
        __syncthreads();

        #pragma unroll
        for (int kk = 0; kk < 16; kk++) {
            float a[8], b[8];
            *(float4*)(a)     = *(const float4*)(&As[kk][ty * 8]);
            *(float4*)(a + 4) = *(const float4*)(&As[kk][ty * 8 + 4]);
            *(float4*)(b)     = *(const float4*)(&Bs[kk][tx * 8]);
            *(float4*)(b + 4) = *(const float4*)(&Bs[kk][tx * 8 + 4]);
            #pragma unroll
            for (int i = 0; i < 8; i++)
                #pragma unroll
                for (int j = 0; j < 8; j++)
                    acc[i][j] += a[i] * b[j];
        }
        __syncthreads();
    }

    #pragma unroll
    for (int i = 0; i < 8; i++) {
        int row = m0 + ty * 8 + i;
        float bb = bias ? bias[row] : 0.f;
        size_t off = (size_t)row * N + n0 + tx * 8;
        float4 v0 = make_float4(acc[i][0] + bb, acc[i][1] + bb, acc[i][2] + bb, acc[i][3] + bb);
        float4 v1 = make_float4(acc[i][4] + bb, acc[i][5] + bb, acc[i][6] + bb, acc[i][7] + bb);
        if (Rb) {
            float4 r0 = *(const float4*)(Rb + off);
            float4 r1 = *(const float4*)(Rb + off + 4);
            v0.x += r0.x; v0.y += r0.y; v0.z += r0.z; v0.w += r0.w;
            v1.x += r1.x; v1.y += r1.y; v1.z += r1.z; v1.w += r1.w;
        }
        *(float4*)(Cb + off)     = v0;
        *(float4*)(Cb + off + 4) = v1;
    }
}

// ---------------------------------------------------------------------------
// S = q @ k^T partial sums. grid (32 bh, QK_NCHUNK n-chunks). Each block does a
// 128x128 output over a 512-slice of the n reduction, atomicAdd into g_attn.
// g_attn must be zeroed first (cudaMemsetAsync).
// ---------------------------------------------------------------------------
__global__ __launch_bounds__(256) void qk_partial() {
    int bh = blockIdx.x, chunk = blockIdx.y;
    int b = bh >> 2, h = bh & 3;
    const float* q = g_qkv + (size_t)b * 3 * CHANNELS * HW + (size_t)h * DHEAD * HW;
    const float* k = q + (size_t)CHANNELS * HW;

    __shared__ float Qs[32][129];  // [n_local][d], padded
    __shared__ float Ks[32][129];

    int t = threadIdx.x, tx = t & 15, ty = t >> 4;
    float acc[8][8] = {};

    int nbeg = chunk * (HW / QK_NCHUNK);
    int nend = nbeg + (HW / QK_NCHUNK);
    for (int n0 = nbeg; n0 < nend; n0 += 32) {
        #pragma unroll
        for (int h2 = 0; h2 < 4; h2++) {
            int idx = t + h2 * 256;
            int row = idx >> 3, c4 = idx & 7;
            float4 v = *(const float4*)(q + (size_t)row * HW + n0 + c4 * 4);
            Qs[c4 * 4 + 0][row] = v.x; Qs[c4 * 4 + 1][row] = v.y;
            Qs[c4 * 4 + 2][row] = v.z; Qs[c4 * 4 + 3][row] = v.w;
            float4 u = *(const float4*)(k + (size_t)row * HW + n0 + c4 * 4);
            Ks[c4 * 4 + 0][row] = u.x; Ks[c4 * 4 + 1][row] = u.y;
            Ks[c4 * 4 + 2][row] = u.z; Ks[c4 * 4 + 3][row] = u.w;
        }
        __syncthreads();
        #pragma unroll
        for (int kk = 0; kk < 32; kk++) {
            float a[8], bb[8];
            #pragma unroll
            for (int i = 0; i < 8; i++) a[i]  = Qs[kk][ty * 8 + i];
            #pragma unroll
            for (int j = 0; j < 8; j++) bb[j] = Ks[kk][tx * 8 + j];
            #pragma unroll
            for (int i = 0; i < 8; i++)
                #pragma unroll
                for (int j = 0; j < 8; j++)
                    acc[i][j] += a[i] * bb[j];
        }
        __syncthreads();
    }

    float* S = g_attn + (size_t)bh * DHEAD * DHEAD;
    #pragma unroll
    for (int i = 0; i < 8; i++)
        #pragma unroll
        for (int j = 0; j < 8; j++)
            atomicAdd(&S[(size_t)(ty * 8 + i) * DHEAD + tx * 8 + j], acc[i][j]);
}

// ---------------------------------------------------------------------------
// Row softmax (scale applied here). One block = one row of 128. In-place.
// ---------------------------------------------------------------------------
__global__ __launch_bounds__(128) void softmax_rows() {
    int row = blockIdx.x;
    float* s = g_attn + (size_t)row * DHEAD;
    int t = threadIdx.x;
    const float scale = 0.08838834764831845f;  // 1/sqrt(128)
    float v = s[t] * scale;

    __shared__ float red[4];
    float m = v;
    #pragma unroll
    for (int o = 16; o; o >>= 1) m = fmaxf(m, __shfl_xor_sync(~0u, m, o));
    if ((t & 31) == 0) red[t >> 5] = m;
    __syncthreads();
    m = fmaxf(fmaxf(red[0], red[1]), fmaxf(red[2], red[3]));

    float e = __expf(v - m);
    float su = e;
    #pragma unroll
    for (int o = 16; o; o >>= 1) su += __shfl_xor_sync(~0u, su, o);
    __syncthreads();
    if ((t & 31) == 0) red[t >> 5] = su;
    __syncthreads();
    su = red[0] + red[1] + red[2] + red[3];
    s[t] = e / su;
}

// ---------------------------------------------------------------------------
// Host launch
// ---------------------------------------------------------------------------
extern "C" void kernel_launch(void* const* d_in, const int* in_sizes, int n_in,
                              void* d_out, int out_size) {
    const float* x      = (const float*)d_in[0];
    const float* gn_w   = (const float*)d_in[1];
    const float* gn_b   = (const float*)d_in[2];
    const float* qkv_w  = (const float*)d_in[3];
    const float* qkv_b  = (const float*)d_in[4];
    const float* proj_w = (const float*)d_in[5];
    const float* proj_b = (const float*)d_in[6];
    float* out = (float*)d_out;

    float *hn, *qkv, *attn;
    cudaGetSymbolAddress((void**)&hn,   g_hn);
    cudaGetSymbolAddress((void**)&qkv,  g_qkv);
    cudaGetSymbolAddress((void**)&attn, g_attn);

    // 1) GroupNorm
    gn_stats<<<BATCH * NGROUPS, 256>>>(x);
    gn_apply<<<(BATCH * CHANNELS * HW) / 4 / 256, 256>>>(x, gn_w, gn_b);

    // 2) QKV GEMM: per b, [1536x512] x [512x4096] (+qkv_b)
    {
        dim3 grid(HW / 128, (3 * CHANNELS) / 128, BATCH);
        sgemm128<<<grid, 256>>>(qkv_w, hn, qkv, qkv_b, nullptr,
                                /*K=*/CHANNELS, /*N=*/HW,
                                /*aStride=*/0,
                                /*bOuter=*/(long)CHANNELS * HW, /*bInner=*/0, /*bInnerN=*/1,
                                /*cStride=*/(long)3 * CHANNELS * HW);
    }

    // 3) S = q k^T (partial-sum over n-chunks, atomicAdd)
    cudaMemsetAsync(attn, 0, (size_t)BATCH * HEADS * DHEAD * DHEAD * sizeof(float), 0);
    {
        dim3 grid(BATCH * HEADS, QK_NCHUNK);
        qk_partial<<<grid, 256>>>();
    }

    // 4) softmax rows (scale + softmax in place)
    softmax_rows<<<BATCH * HEADS * DHEAD, 128>>>();

    // 5) AV GEMM: per bh, [128x128] x [128x4096] -> g_hn (reused)
    {
        dim3 grid(HW / 128, 1, BATCH * HEADS);
        // v base = g_qkv + 2*CHANNELS*HW within each batch
        sgemm128<<<grid, 256>>>(attn, qkv + (size_t)2 * CHANNELS * HW, hn,
                                nullptr, nullptr,
                                /*K=*/DHEAD, /*N=*/HW,
                                /*aStride=*/(long)DHEAD * DHEAD,
                                /*bOuter=*/(long)3 * CHANNELS * HW,
                                /*bInner=*/(long)DHEAD * HW, /*bInnerN=*/HEADS,
                                /*cStride=*/(long)DHEAD * HW);
    }

    // 6) proj GEMM + bias + residual -> out
    {
        dim3 grid(HW / 128, CHANNELS / 128, BATCH);
        sgemm128<<<grid, 256>>>(proj_w, hn, out, proj_b, x,
                                /*K=*/CHANNELS, /*N=*/HW,
                                /*aStride=*/0,
                                /*bOuter=*/(long)CHANNELS * HW, /*bInner=*/0, /*bInnerN=*/1,
                                /*cStride=*/(long)CHANNELS * HW);
    }
    (void)in_sizes; (void)n_in; (void)out_size;
}

// round 5
// speedup vs baseline: 2.5924x; 2.5924x over previous
#include <cuda_runtime.h>
#include <cuda_fp16.h>
#include <cstdint>

#define BATCH  8
#define CH     512
#define HW     4096
#define HEADS  4
#define DH     128
#define NG     32
#define EPS    1e-5f

// ---------------- scratch (device globals; allocation-free) ----------------
__device__ __align__(1024) __half g_hnT[(size_t)BATCH * HW * CH];   // [b][n][c]
__device__ __align__(1024) __half g_qk [(size_t)BATCH * 1024 * HW]; // [b][o<1024][n] q,k
__device__ __align__(1024) __half g_vT [(size_t)BATCH * HW * CH];   // [b][n][e] (e=vo 0..511)
__device__ __align__(1024) __half g_at [(size_t)BATCH * HEADS * DH * DH]; // [bh][d][e]
__device__ __align__(1024) __half g_aoT[(size_t)BATCH * HW * CH];   // [b][n][c]
__device__ __align__(1024) __half g_w16[(size_t)4 * CH * CH];       // qkv_w then proj_w
__device__ float g_mean[BATCH * NG], g_rstd[BATCH * NG];

// ---------------- helpers ----------------
__device__ __forceinline__ uint32_t smem_u32(const void* p) {
    uint32_t a;
    asm("{ .reg .u64 t; cvta.to.shared.u64 t, %1; cvt.u32.u64 %0, t; }" : "=r"(a) : "l"(p));
    return a;
}
#define CPA16(sa, gp) \
    asm volatile("cp.async.cg.shared.global [%0], [%1], 16;" :: "r"(sa), "l"(gp))
#define CP_COMMIT() asm volatile("cp.async.commit_group;" ::: "memory")
#define CP_WAIT(n)  asm volatile("cp.async.wait_group %0;" :: "n"(n) : "memory")

// SMEM tile: 128 rows x 32 halves, padded row stride 40 halves (80B) -> conflict-free ldmatrix
#define TPAD   40
#define TBYTES (128 * TPAD * 2)   // 10240

__device__ __forceinline__ void load_slab(uint32_t sbase, const __half* g, size_t stride, int tid) {
    #pragma unroll
    for (int i = 0; i < 2; i++) {
        int idx = tid + i * 256;
        int row = idx >> 2, ch = idx & 3;
        CPA16(sbase + row * (TPAD * 2) + ch * 16, g + (size_t)row * stride + ch * 8);
    }
}

// Block GEMM: D[128 m][128 n] = A[128 rows,K] x B[128 rows,K], both K-major.
// 256 threads, 8 warps (2m x 4n), warp tile 64x32, fp32 accum.
__device__ __forceinline__ void hgemm_block(const __half* __restrict__ A, size_t sA,
                                            const __half* __restrict__ B, size_t sB,
                                            int K, char* sm, float acc[4][4][4]) {
    uint32_t Ab = smem_u32(sm);
    uint32_t Bb = Ab + 2 * TBYTES;
    int tid = threadIdx.x, lane = tid & 31, w = tid >> 5;
    int wm = w & 1, wn = w >> 1;

    #pragma unroll
    for (int i = 0; i < 4; i++)
        #pragma unroll
        for (int j = 0; j < 4; j++)
            #pragma unroll
            for (int e = 0; e < 4; e++) acc[i][j][e] = 0.f;

    const int S = K >> 5;
    load_slab(Ab, A, sA, tid);
    load_slab(Bb, B, sB, tid);
    CP_COMMIT();

    for (int s = 0; s < S; s++) {
        int buf = s & 1;
        if (s + 1 < S) {
            load_slab(Ab + (buf ^ 1) * TBYTES, A + (size_t)(s + 1) * 32, sA, tid);
            load_slab(Bb + (buf ^ 1) * TBYTES, B + (size_t)(s + 1) * 32, sB, tid);
            CP_COMMIT();
            CP_WAIT(1);
        } else {
            CP_WAIT(0);
        }
        __syncthreads();

        uint32_t Abase = Ab + buf * TBYTES;
        uint32_t Bbase = Bb + buf * TBYTES;
        #pragma unroll
        for (int kk = 0; kk < 2; kk++) {
            uint32_t af[4][4], bf[4][2];
            #pragma unroll
            for (int mf = 0; mf < 4; mf++) {
                int r  = wm * 64 + mf * 16 + (lane & 7) + ((lane >> 3) & 1) * 8;
                int cb = kk * 32 + (lane >> 4) * 16;
                uint32_t ad = Abase + r * (TPAD * 2) + cb;
                asm volatile("ldmatrix.sync.aligned.m8n8.x4.shared.b16 {%0,%1,%2,%3}, [%4];"
                    : "=r"(af[mf][0]), "=r"(af[mf][1]), "=r"(af[mf][2]), "=r"(af[mf][3])
                    : "r"(ad));
            }
            #pragma unroll
            for (int nf = 0; nf < 4; nf++) {
                int r  = wn * 32 + nf * 8 + (lane & 7);
                int cb = kk * 32 + ((lane >> 3) & 1) * 16;
                uint32_t bd = Bbase + r * (TPAD * 2) + cb;
                asm volatile("ldmatrix.sync.aligned.m8n8.x2.shared.b16 {%0,%1}, [%2];"
                    : "=r"(bf[nf][0]), "=r"(bf[nf][1]) : "r"(bd));
            }
            #pragma unroll
            for (int mf = 0; mf < 4; mf++)
                #pragma unroll
                for (int nf = 0; nf < 4; nf++) {
                    float* c = acc[mf][nf];
                    asm volatile(
                        "mma.sync.aligned.m16n8k16.row.col.f32.f16.f16.f32 "
                        "{%0,%1,%2,%3}, {%4,%5,%6,%7}, {%8,%9}, {%0,%1,%2,%3};"
                        : "+f"(c[0]), "+f"(c[1]), "+f"(c[2]), "+f"(c[3])
                        : "r"(af[mf][0]), "r"(af[mf][1]), "r"(af[mf][2]), "r"(af[mf][3]),
                          "r"(bf[nf][0]), "r"(bf[nf][1]));
                }
        }
        __syncthreads();
    }
}

// ---------------- GroupNorm ----------------
#define GSZ (CH / NG * HW)   // 65536 contiguous per (b,g)
__global__ __launch_bounds__(256) void gn_stats(const float* __restrict__ x) {
    int bg = blockIdx.x;
    const float4* p = (const float4*)(x + (size_t)bg * GSZ);
    float s = 0.f, sq = 0.f;
    for (int i = threadIdx.x; i < GSZ / 4; i += 256) {
        float4 v = p[i];
        s  += v.x + v.y + v.z + v.w;
        sq += v.x * v.x + v.y * v.y + v.z * v.z + v.w * v.w;
    }
    __shared__ float ss[8], sr[8];
    #pragma unroll
    for (int o = 16; o; o >>= 1) { s += __shfl_down_sync(~0u, s, o); sq += __shfl_down_sync(~0u, sq, o); }
    int w = threadIdx.x >> 5, l = threadIdx.x & 31;
    if (l == 0) { ss[w] = s; sr[w] = sq; }
    __syncthreads();
    if (w == 0) {
        s  = (l < 8) ? ss[l] : 0.f;
        sq = (l < 8) ? sr[l] : 0.f;
        #pragma unroll
        for (int o = 4; o; o >>= 1) { s += __shfl_down_sync(~0u, s, o); sq += __shfl_down_sync(~0u, sq, o); }
        if (l == 0) {
            float mu = s * (1.f / GSZ);
            float va = sq * (1.f / GSZ) - mu * mu;
            g_mean[bg] = mu;
            g_rstd[bg] = rsqrtf(va + EPS);
        }
    }
}

__global__ __launch_bounds__(256) void gn_apply_T(const float* __restrict__ x,
                                                  const float* __restrict__ gw,
                                                  const float* __restrict__ gb) {
    __shared__ float t[32][33];
    int b = blockIdx.z, c0 = blockIdx.y * 32, n0 = blockIdx.x * 32;
    int tx = threadIdx.x, ty = threadIdx.y;   // 32 x 8
    #pragma unroll
    for (int i = 0; i < 4; i++) {
        int c  = c0 + ty + i * 8;
        int bg = b * NG + (c >> 4);
        float r = g_rstd[bg];
        float w = gw[c] * r;
        float bb = gb[c] - g_mean[bg] * w;
        t[ty + i * 8][tx] = x[((size_t)b * CH + c) * HW + n0 + tx] * w + bb;
    }
    __syncthreads();
    #pragma unroll
    for (int i = 0; i < 4; i++) {
        int n = n0 + ty + i * 8;
        g_hnT[((size_t)b * HW + n) * CH + c0 + tx] = __float2half_rn(t[tx][ty + i * 8]);
    }
}

__global__ __launch_bounds__(256) void conv16(const float* __restrict__ s, __half* __restrict__ d, int n) {
    int i = blockIdx.x * 256 + threadIdx.x;
    if (i < n) d[i] = __float2half_rn(s[i]);
}

// ---------------- QKV: D[o][n] = qkv_w x hn ----------------
__global__ __launch_bounds__(256) void k_qkv(const float* __restrict__ qkv_b) {
    extern __shared__ char sm[];
    int n0 = blockIdx.x * 128, o0 = blockIdx.y * 128, b = blockIdx.z;
    float acc[4][4][4];
    hgemm_block(g_w16 + (size_t)o0 * CH, CH,
                g_hnT + ((size_t)b * HW + n0) * CH, CH, CH, sm, acc);

    int tid = threadIdx.x, lane = tid & 31, w = tid >> 5;
    int wm = w & 1, wn = w >> 1, g = lane >> 2, ti = lane & 3;

    if (o0 < 1024) {   // q,k: direct coalesced [o][n] stores
        #pragma unroll
        for (int mf = 0; mf < 4; mf++) {
            int oa = o0 + wm * 64 + mf * 16 + g;
            float ba = qkv_b[oa], bb = qkv_b[oa + 8];
            #pragma unroll
            for (int nf = 0; nf < 4; nf++) {
                int n = n0 + wn * 32 + nf * 8 + ti * 2;
                float* c = acc[mf][nf];
                *(__half2*)(g_qk + ((size_t)(b * 1024 + oa)) * HW + n) =
                    __floats2half2_rn(c[0] + ba, c[1] + ba);
                *(__half2*)(g_qk + ((size_t)(b * 1024 + oa + 8)) * HW + n) =
                    __floats2half2_rn(c[2] + bb, c[3] + bb);
            }
        }
    } else {           // v: transpose via SMEM -> vT[n][e]
        __half* Ts = (__half*)sm;
        #pragma unroll
        for (int mf = 0; mf < 4; mf++) {
            int ol = wm * 64 + mf * 16 + g;
            float ba = qkv_b[o0 + ol], bb = qkv_b[o0 + ol + 8];
            #pragma unroll
            for (int nf = 0; nf < 4; nf++) {
                int nl = wn * 32 + nf * 8 + ti * 2;
                float* c = acc[mf][nf];
                Ts[(nl    ) * 136 + ol    ] = __float2half_rn(c[0] + ba);
                Ts[(nl + 1) * 136 + ol    ] = __float2half_rn(c[1] + ba);
                Ts[(nl    ) * 136 + ol + 8] = __float2half_rn(c[2] + bb);
                Ts[(nl + 1) * 136 + ol + 8] = __float2half_rn(c[3] + bb);
            }
        }
        __syncthreads();
        int r = tid >> 1, part = tid & 1;
        uint4* dst = (uint4*)(g_vT + ((size_t)b * HW + n0 + r) * CH + (o0 - 1024) + part * 64);
        const uint4* src = (const uint4*)(Ts + r * 136 + part * 64);
        #pragma unroll
        for (int j = 0; j < 8; j++) dst[j] = src[j];
    }
}

// ---------------- QK^T + fused softmax ----------------
__global__ __launch_bounds__(256) void k_qks() {
    extern __shared__ char sm[];
    int bh = blockIdx.x, b = bh >> 2, h = bh & 3;
    float acc[4][4][4];
    hgemm_block(g_qk + ((size_t)(b * 1024 + h * DH)) * HW, HW,
                g_qk + ((size_t)(b * 1024 + 512 + h * DH)) * HW, HW, HW, sm, acc);

    float* Ss = (float*)sm;   // [128][130]
    int tid = threadIdx.x, lane = tid & 31, w = tid >> 5;
    int wm = w & 1, wn = w >> 1, g = lane >> 2, ti = lane & 3;
    #pragma unroll
    for (int mf = 0; mf < 4; mf++) {
        int ml = wm * 64 + mf * 16 + g;
        #pragma unroll
        for (int nf = 0; nf < 4; nf++) {
            int nl = wn * 32 + nf * 8 + ti * 2;
            float* c = acc[mf][nf];
            *(float2*)(Ss + (size_t)ml * 130 + nl)       = make_float2(c[0], c[1]);
            *(float2*)(Ss + (size_t)(ml + 8) * 130 + nl) = make_float2(c[2], c[3]);
        }
    }
    __syncthreads();
    if (tid < 128) {
        const float scale = 0.08838834764831845f;   // 128^-0.5
        float v[128], mx = -1e30f;
        #pragma unroll
        for (int i = 0; i < 128; i++) { v[i] = Ss[(size_t)tid * 130 + i] * scale; mx = fmaxf(mx, v[i]); }
        float su = 0.f;
        #pragma unroll
        for (int i = 0; i < 128; i++) { v[i] = __expf(v[i] - mx); su += v[i]; }
        float inv = 1.f / su;
        __half2* dst = (__half2*)(g_at + ((size_t)bh * DH + tid) * DH);
        #pragma unroll
        for (int j = 0; j < 64; j++)
            dst[j] = __floats2half2_rn(v[2 * j] * inv, v[2 * j + 1] * inv);
    }
}

// ---------------- AV: ao[d][n] -> aoT[n][c] ----------------
__global__ __launch_bounds__(256) void k_av() {
    extern __shared__ char sm[];
    int n0 = blockIdx.x * 128, bh = blockIdx.z, b = bh >> 2, h = bh & 3;
    float acc[4][4][4];
    hgemm_block(g_at + (size_t)bh * DH * DH, DH,
                g_vT + ((size_t)b * HW + n0) * CH + h * DH, CH, DH, sm, acc);

    __half* Ts = (__half*)sm;
    int tid = threadIdx.x, lane = tid & 31, w = tid >> 5;
    int wm = w & 1, wn = w >> 1, g = lane >> 2, ti = lane & 3;
    #pragma unroll
    for (int mf = 0; mf < 4; mf++) {
        int dl = wm * 64 + mf * 16 + g;
        #pragma unroll
        for (int nf = 0; nf < 4; nf++) {
            int nl = wn * 32 + nf * 8 + ti * 2;
            float* c = acc[mf][nf];
            Ts[(nl    ) * 136 + dl    ] = __float2half_rn(c[0]);
            Ts[(nl + 1) * 136 + dl    ] = __float2half_rn(c[1]);
            Ts[(nl    ) * 136 + dl + 8] = __float2half_rn(c[2]);
            Ts[(nl + 1) * 136 + dl + 8] = __float2half_rn(c[3]);
        }
    }
    __syncthreads();
    int r = tid >> 1, part = tid & 1;
    uint4* dst = (uint4*)(g_aoT + ((size_t)b * HW + n0 + r) * CH + h * DH + part * 64);
    const uint4* src = (const uint4*)(Ts + r * 136 + part * 64);
    #pragma unroll
    for (int j = 0; j < 8; j++) dst[j] = src[j];
}

// ---------------- proj + bias + residual ----------------
__global__ __launch_bounds__(256) void k_proj(const float* __restrict__ proj_b,
                                              const float* __restrict__ x,
                                              float* __restrict__ out) {
    extern __shared__ char sm[];
    int n0 = blockIdx.x * 128, o0 = blockIdx.y * 128, b = blockIdx.z;
    float acc[4][4][4];
    hgemm_block(g_w16 + (size_t)3 * CH * CH + (size_t)o0 * CH, CH,
                g_aoT + ((size_t)b * HW + n0) * CH, CH, CH, sm, acc);

    int tid = threadIdx.x, lane = tid & 31, w = tid >> 5;
    int wm = w & 1, wn = w >> 1, g = lane >> 2, ti = lane & 3;
    #pragma unroll
    for (int mf = 0; mf < 4; mf++) {
        int oa = o0 + wm * 64 + mf * 16 + g;
        float ba = proj_b[oa], bb = proj_b[oa + 8];
        #pragma unroll
        for (int nf = 0; nf < 4; nf++) {
            int n = n0 + wn * 32 + nf * 8 + ti * 2;
            float* c = acc[mf][nf];
            size_t o1 = ((size_t)b * CH + oa) * HW + n;
            size_t o2 = ((size_t)b * CH + oa + 8) * HW + n;
            float2 r1 = *(const float2*)(x + o1);
            float2 r2 = *(const float2*)(x + o2);
            *(float2*)(out + o1) = make_float2(c[0] + ba + r1.x, c[1] + ba + r1.y);
            *(float2*)(out + o2) = make_float2(c[2] + bb + r2.x, c[3] + bb + r2.y);
        }
    }
}

// ---------------- host ----------------
#define SMEM_GEMM 40960    // 4 tile buffers (also covers 34816B transpose staging)
#define SMEM_QK   66560    // 128x130 fp32 softmax staging

extern "C" void kernel_launch(void* const* d_in, const int* in_sizes, int n_in,
                              void* d_out, int out_size) {
    const float* x      = (const float*)d_in[0];
    const float* gn_w   = (const float*)d_in[1];
    const float* gn_b   = (const float*)d_in[2];
    const float* qkv_w  = (const float*)d_in[3];
    const float* qkv_b  = (const float*)d_in[4];
    const float* proj_w = (const float*)d_in[5];
    const float* proj_b = (const float*)d_in[6];
    float* out = (float*)d_out;

    cudaFuncSetAttribute(k_qkv,  cudaFuncAttributeMaxDynamicSharedMemorySize, SMEM_GEMM);
    cudaFuncSetAttribute(k_qks,  cudaFuncAttributeMaxDynamicSharedMemorySize, SMEM_QK);
    cudaFuncSetAttribute(k_av,   cudaFuncAttributeMaxDynamicSharedMemorySize, SMEM_GEMM);
    cudaFuncSetAttribute(k_proj, cudaFuncAttributeMaxDynamicSharedMemorySize, SMEM_GEMM);

    __half* w16;
    cudaGetSymbolAddress((void**)&w16, g_w16);

    gn_stats<<<BATCH * NG, 256>>>(x);
    gn_apply_T<<<dim3(HW / 32, CH / 32, BATCH), dim3(32, 8)>>>(x, gn_w, gn_b);
    conv16<<<(3 * CH * CH + 255) / 256, 256>>>(qkv_w, w16, 3 * CH * CH);
    conv16<<<(CH * CH + 255) / 256, 256>>>(proj_w, w16 + (size_t)3 * CH * CH, CH * CH);

    k_qkv <<<dim3(HW / 128, 12, BATCH), 256, SMEM_GEMM>>>(qkv_b);
    k_qks <<<BATCH * HEADS, 256, SMEM_QK>>>();
    k_av  <<<dim3(HW / 128, 1, BATCH * HEADS), 256, SMEM_GEMM>>>();
    k_proj<<<dim3(HW / 128, CH / 128, BATCH), 256, SMEM_GEMM>>>(proj_b, x, out);

    (void)in_sizes; (void)n_in; (void)out_size;
}

// round 6
// speedup vs baseline: 3.8716x; 1.4934x over previous
#include <cuda_runtime.h>
#include <cuda_fp16.h>
#include <cstdint>

#define BATCH  8
#define CH     512
#define HW     4096
#define HEADS  4
#define DH     128
#define NG     32
#define EPS    1e-5f

// ---------------- scratch (device globals; allocation-free) ----------------
__device__ __align__(1024) __half g_hnT[(size_t)BATCH * HW * CH];   // [b][n][c]
__device__ __align__(1024) __half g_qk [(size_t)BATCH * 1024 * HW]; // [b][o<1024][n] q,k
__device__ __align__(1024) __half g_vT [(size_t)BATCH * HW * CH];   // [b][n][e]
__device__ __align__(1024) __half g_at [(size_t)BATCH * HEADS * DH * DH]; // [bh][d][e]
__device__ __align__(1024) __half g_aoT[(size_t)BATCH * HW * CH];   // [b][n][c]
__device__ __align__(1024) __half g_w16[(size_t)4 * CH * CH];       // qkv_w then proj_w
__device__ float g_mean[BATCH * NG], g_rstd[BATCH * NG];

// ---------------- helpers ----------------
__device__ __forceinline__ uint32_t smem_u32(const void* p) {
    uint32_t a;
    asm("{ .reg .u64 t; cvta.to.shared.u64 t, %1; cvt.u32.u64 %0, t; }" : "=r"(a) : "l"(p));
    return a;
}
#define CPA16(sa, gp) \
    asm volatile("cp.async.cg.shared.global [%0], [%1], 16;" :: "r"(sa), "l"(gp))
#define CP_COMMIT() asm volatile("cp.async.commit_group;" ::: "memory")
#define CP_WAIT(n)  asm volatile("cp.async.wait_group %0;" :: "n"(n) : "memory")

// SMEM tile rows: 32 halves (64B) payload, padded row stride 80B (conflict-free ldmatrix)
#define RB 80

template<int R>
__device__ __forceinline__ void load_tile(uint32_t sb, const __half* __restrict__ g,
                                          size_t stride, int tid) {
    #pragma unroll
    for (int i = 0; i < R / 64; i++) {
        int idx = tid + i * 256, row = idx >> 2, ch = idx & 3;
        CPA16(sb + row * RB + ch * 16, g + (size_t)row * stride + ch * 8);
    }
}

// Block GEMM: D[128 m][4*WN n] = A[128,K] x B[4*WN,K], both K-major, 256 thr, 8 warps (2m x 4n),
// warp tile 64 x WN, fp32 accum (flattened acc[(mf*NF+nf)*4+e]). 3-stage cp.async pipeline.
// NOTE: no trailing barrier — callers must __syncthreads() before reusing smem.
template<int WN>
__device__ __forceinline__ void hgemm_block(const __half* __restrict__ A, size_t sA,
                                            const __half* __restrict__ B, size_t sB,
                                            int K, char* sm, float* acc) {
    constexpr int NF = WN / 8;
    constexpr int NT = 4 * WN;
    constexpr int ABYTES = 128 * RB;
    constexpr int BBYTES = NT * RB;
    constexpr int STAGE  = ABYTES + BBYTES;
    uint32_t s0 = smem_u32(sm);
    int tid = threadIdx.x, lane = tid & 31, w = tid >> 5;
    int wm = w & 1, wn = w >> 1;

    #pragma unroll
    for (int i = 0; i < 16 * NF; i++) acc[i] = 0.f;

    const int S = K >> 5;
    load_tile<128>(s0, A, sA, tid);
    load_tile<NT >(s0 + ABYTES, B, sB, tid);
    CP_COMMIT();
    if (S > 1) {
        load_tile<128>(s0 + STAGE, A + 32, sA, tid);
        load_tile<NT >(s0 + STAGE + ABYTES, B + 32, sB, tid);
        CP_COMMIT();
    }

    int slot_c = 0, slot_p = 2 % 3;
    for (int s = 0; s < S; s++) {
        if (s + 1 < S) CP_WAIT(1); else CP_WAIT(0);
        __syncthreads();
        if (s + 2 < S) {
            load_tile<128>(s0 + slot_p * STAGE, A + (size_t)(s + 2) * 32, sA, tid);
            load_tile<NT >(s0 + slot_p * STAGE + ABYTES, B + (size_t)(s + 2) * 32, sB, tid);
            CP_COMMIT();
        }
        uint32_t Ab = s0 + slot_c * STAGE;
        uint32_t Bb = Ab + ABYTES;
        slot_c = (slot_c + 1 == 3) ? 0 : slot_c + 1;
        slot_p = (slot_p + 1 == 3) ? 0 : slot_p + 1;

        #pragma unroll
        for (int kk = 0; kk < 2; kk++) {
            uint32_t af[4][4], bf[NF][2];
            #pragma unroll
            for (int mf = 0; mf < 4; mf++) {
                int r  = wm * 64 + mf * 16 + (lane & 7) + ((lane >> 3) & 1) * 8;
                int cb = kk * 32 + (lane >> 4) * 16;
                asm volatile("ldmatrix.sync.aligned.m8n8.x4.shared.b16 {%0,%1,%2,%3}, [%4];"
                    : "=r"(af[mf][0]), "=r"(af[mf][1]), "=r"(af[mf][2]), "=r"(af[mf][3])
                    : "r"(Ab + r * RB + cb));
            }
            #pragma unroll
            for (int p = 0; p < NF / 2; p++) {
                int r  = wn * WN + p * 16 + (lane >> 4) * 8 + (lane & 7);
                int cb = kk * 32 + ((lane >> 3) & 1) * 16;
                asm volatile("ldmatrix.sync.aligned.m8n8.x4.shared.b16 {%0,%1,%2,%3}, [%4];"
                    : "=r"(bf[2 * p][0]), "=r"(bf[2 * p][1]),
                      "=r"(bf[2 * p + 1][0]), "=r"(bf[2 * p + 1][1])
                    : "r"(Bb + r * RB + cb));
            }
            #pragma unroll
            for (int mf = 0; mf < 4; mf++)
                #pragma unroll
                for (int nf = 0; nf < NF; nf++) {
                    float* c = acc + (mf * NF + nf) * 4;
                    asm volatile(
                        "mma.sync.aligned.m16n8k16.row.col.f32.f16.f16.f32 "
                        "{%0,%1,%2,%3}, {%4,%5,%6,%7}, {%8,%9}, {%0,%1,%2,%3};"
                        : "+f"(c[0]), "+f"(c[1]), "+f"(c[2]), "+f"(c[3])
                        : "r"(af[mf][0]), "r"(af[mf][1]), "r"(af[mf][2]), "r"(af[mf][3]),
                          "r"(bf[nf][0]), "r"(bf[nf][1]));
                }
        }
    }
}

// ---------------- GroupNorm ----------------
#define GSZ (CH / NG * HW)
__global__ __launch_bounds__(256) void gn_stats(const float* __restrict__ x) {
    int bg = blockIdx.x;
    const float4* p = (const float4*)(x + (size_t)bg * GSZ);
    float s = 0.f, sq = 0.f;
    for (int i = threadIdx.x; i < GSZ / 4; i += 256) {
        float4 v = p[i];
        s  += v.x + v.y + v.z + v.w;
        sq += v.x * v.x + v.y * v.y + v.z * v.z + v.w * v.w;
    }
    __shared__ float ss[8], sr[8];
    #pragma unroll
    for (int o = 16; o; o >>= 1) { s += __shfl_down_sync(~0u, s, o); sq += __shfl_down_sync(~0u, sq, o); }
    int w = threadIdx.x >> 5, l = threadIdx.x & 31;
    if (l == 0) { ss[w] = s; sr[w] = sq; }
    __syncthreads();
    if (w == 0) {
        s  = (l < 8) ? ss[l] : 0.f;
        sq = (l < 8) ? sr[l] : 0.f;
        #pragma unroll
        for (int o = 4; o; o >>= 1) { s += __shfl_down_sync(~0u, s, o); sq += __shfl_down_sync(~0u, sq, o); }
        if (l == 0) {
            float mu = s * (1.f / GSZ);
            float va = sq * (1.f / GSZ) - mu * mu;
            g_mean[bg] = mu;
            g_rstd[bg] = rsqrtf(va + EPS);
        }
    }
}

__global__ __launch_bounds__(256) void gn_apply_T(const float* __restrict__ x,
                                                  const float* __restrict__ gw,
                                                  const float* __restrict__ gb) {
    __shared__ float t[32][33];
    int b = blockIdx.z, c0 = blockIdx.y * 32, n0 = blockIdx.x * 32;
    int tx = threadIdx.x, ty = threadIdx.y;   // 32 x 8
    #pragma unroll
    for (int i = 0; i < 4; i++) {
        int c  = c0 + ty + i * 8;
        int bg = b * NG + (c >> 4);
        float r = g_rstd[bg];
        float w = gw[c] * r;
        float bb = gb[c] - g_mean[bg] * w;
        t[ty + i * 8][tx] = x[((size_t)b * CH + c) * HW + n0 + tx] * w + bb;
    }
    __syncthreads();
    #pragma unroll
    for (int i = 0; i < 4; i++) {
        int n = n0 + ty + i * 8;
        g_hnT[((size_t)b * HW + n) * CH + c0 + tx] = __float2half_rn(t[tx][ty + i * 8]);
    }
}

__global__ __launch_bounds__(256) void conv_w(const float* __restrict__ qw,
                                              const float* __restrict__ pw) {
    int i = blockIdx.x * 256 + threadIdx.x;
    const int NQ = 3 * CH * CH;
    float v = (i < NQ) ? qw[i] : pw[i - NQ];
    g_w16[i] = __float2half_rn(v);
}

// ---------------- QKV: D[o][n] = qkv_w x hn  (128m x 256n tiles) ----------------
__global__ __launch_bounds__(256, 1) void k_qkv(const float* __restrict__ qkv_b) {
    extern __shared__ char sm[];
    int n0 = blockIdx.x * 256, o0 = blockIdx.y * 128, b = blockIdx.z;
    float acc[128];
    hgemm_block<64>(g_w16 + (size_t)o0 * CH, CH,
                    g_hnT + ((size_t)b * HW + n0) * CH, CH, CH, sm, acc);

    int tid = threadIdx.x, lane = tid & 31, w = tid >> 5;
    int wm = w & 1, wn = w >> 1, g = lane >> 2, ti = lane & 3;

    if (o0 < 1024) {   // q,k: coalesced direct [o][n] stores
        #pragma unroll
        for (int mf = 0; mf < 4; mf++) {
            int oa = o0 + wm * 64 + mf * 16 + g;
            float ba = qkv_b[oa], bb = qkv_b[oa + 8];
            #pragma unroll
            for (int nf = 0; nf < 8; nf++) {
                int n = n0 + wn * 64 + nf * 8 + ti * 2;
                float* c = acc + (mf * 8 + nf) * 4;
                *(__half2*)(g_qk + ((size_t)(b * 1024 + oa)) * HW + n) =
                    __floats2half2_rn(c[0] + ba, c[1] + ba);
                *(__half2*)(g_qk + ((size_t)(b * 1024 + oa + 8)) * HW + n) =
                    __floats2half2_rn(c[2] + bb, c[3] + bb);
            }
        }
    } else {           // v: transpose via SMEM -> vT[n][e]
        __syncthreads();
        __half* Ts = (__half*)sm;   // [256 n][136]
        #pragma unroll
        for (int mf = 0; mf < 4; mf++) {
            int ol = wm * 64 + mf * 16 + g;
            float ba = qkv_b[o0 + ol], bb = qkv_b[o0 + ol + 8];
            #pragma unroll
            for (int nf = 0; nf < 8; nf++) {
                int nl = wn * 64 + nf * 8 + ti * 2;
                float* c = acc + (mf * 8 + nf) * 4;
                Ts[(nl    ) * 136 + ol    ] = __float2half_rn(c[0] + ba);
                Ts[(nl + 1) * 136 + ol    ] = __float2half_rn(c[1] + ba);
                Ts[(nl    ) * 136 + ol + 8] = __float2half_rn(c[2] + bb);
                Ts[(nl + 1) * 136 + ol + 8] = __float2half_rn(c[3] + bb);
            }
        }
        __syncthreads();
        uint4* dst = (uint4*)(g_vT + ((size_t)b * HW + n0 + tid) * CH + (o0 - 1024));
        const uint4* src = (const uint4*)(Ts + tid * 136);
        #pragma unroll
        for (int j = 0; j < 16; j++) dst[j] = src[j];
    }
}

// ---------------- QK^T + fused softmax (128x128) ----------------
__global__ __launch_bounds__(256, 1) void k_qks() {
    extern __shared__ char sm[];
    int bh = blockIdx.x, b = bh >> 2, h = bh & 3;
    float acc[64];
    hgemm_block<32>(g_qk + ((size_t)(b * 1024 + h * DH)) * HW, HW,
                    g_qk + ((size_t)(b * 1024 + 512 + h * DH)) * HW, HW, HW, sm, acc);
    __syncthreads();

    float* Ss = (float*)sm;   // [128][130]
    int tid = threadIdx.x, lane = tid & 31, w = tid >> 5;
    int wm = w & 1, wn = w >> 1, g = lane >> 2, ti = lane & 3;
    #pragma unroll
    for (int mf = 0; mf < 4; mf++) {
        int ml = wm * 64 + mf * 16 + g;
        #pragma unroll
        for (int nf = 0; nf < 4; nf++) {
            int nl = wn * 32 + nf * 8 + ti * 2;
            float* c = acc + (mf * 4 + nf) * 4;
            *(float2*)(Ss + (size_t)ml * 130 + nl)       = make_float2(c[0], c[1]);
            *(float2*)(Ss + (size_t)(ml + 8) * 130 + nl) = make_float2(c[2], c[3]);
        }
    }
    __syncthreads();
    {
        int row = tid >> 1, half = tid & 1;
        const float scale = 0.08838834764831845f;
        float v[64], mx = -1e30f;
        #pragma unroll
        for (int i = 0; i < 64; i++) { v[i] = Ss[(size_t)row * 130 + half * 64 + i] * scale; mx = fmaxf(mx, v[i]); }
        mx = fmaxf(mx, __shfl_xor_sync(~0u, mx, 1));
        float su = 0.f;
        #pragma unroll
        for (int i = 0; i < 64; i++) { v[i] = __expf(v[i] - mx); su += v[i]; }
        su += __shfl_xor_sync(~0u, su, 1);
        float inv = 1.f / su;
        __half2* dst = (__half2*)(g_at + ((size_t)bh * DH + row) * DH + half * 64);
        #pragma unroll
        for (int j = 0; j < 32; j++)
            dst[j] = __floats2half2_rn(v[2 * j] * inv, v[2 * j + 1] * inv);
    }
}

// ---------------- AV: ao[d][n] -> aoT[n][c] ----------------
__global__ __launch_bounds__(256, 1) void k_av() {
    extern __shared__ char sm[];
    int n0 = blockIdx.x * 128, bh = blockIdx.z, b = bh >> 2, h = bh & 3;
    float acc[64];
    hgemm_block<32>(g_at + (size_t)bh * DH * DH, DH,
                    g_vT + ((size_t)b * HW + n0) * CH + h * DH, CH, DH, sm, acc);
    __syncthreads();

    __half* Ts = (__half*)sm;   // [128 n][136]
    int tid = threadIdx.x, lane = tid & 31, w = tid >> 5;
    int wm = w & 1, wn = w >> 1, g = lane >> 2, ti = lane & 3;
    #pragma unroll
    for (int mf = 0; mf < 4; mf++) {
        int dl = wm * 64 + mf * 16 + g;
        #pragma unroll
        for (int nf = 0; nf < 4; nf++) {
            int nl = wn * 32 + nf * 8 + ti * 2;
            float* c = acc + (mf * 4 + nf) * 4;
            Ts[(nl    ) * 136 + dl    ] = __float2half_rn(c[0]);
            Ts[(nl + 1) * 136 + dl    ] = __float2half_rn(c[1]);
            Ts[(nl    ) * 136 + dl + 8] = __float2half_rn(c[2]);
            Ts[(nl + 1) * 136 + dl + 8] = __float2half_rn(c[3]);
        }
    }
    __syncthreads();
    int r = tid >> 1, part = tid & 1;
    uint4* dst = (uint4*)(g_aoT + ((size_t)b * HW + n0 + r) * CH + h * DH + part * 64);
    const uint4* src = (const uint4*)(Ts + r * 136 + part * 64);
    #pragma unroll
    for (int j = 0; j < 8; j++) dst[j] = src[j];
}

// ---------------- proj + bias + residual (128m x 256n tiles) ----------------
__global__ __launch_bounds__(256, 1) void k_proj(const float* __restrict__ proj_b,
                                                 const float* __restrict__ x,
                                                 float* __restrict__ out) {
    extern __shared__ char sm[];
    int n0 = blockIdx.x * 256, o0 = blockIdx.y * 128, b = blockIdx.z;
    float acc[128];
    hgemm_block<64>(g_w16 + (size_t)3 * CH * CH + (size_t)o0 * CH, CH,
                    g_aoT + ((size_t)b * HW + n0) * CH, CH, CH, sm, acc);

    int tid = threadIdx.x, lane = tid & 31, w = tid >> 5;
    int wm = w & 1, wn = w >> 1, g = lane >> 2, ti = lane & 3;
    #pragma unroll
    for (int mf = 0; mf < 4; mf++) {
        int oa = o0 + wm * 64 + mf * 16 + g;
        float ba = proj_b[oa], bb = proj_b[oa + 8];
        #pragma unroll
        for (int nf = 0; nf < 8; nf++) {
            int n = n0 + wn * 64 + nf * 8 + ti * 2;
            float* c = acc + (mf * 8 + nf) * 4;
            size_t o1 = ((size_t)b * CH + oa) * HW + n;
            size_t o2 = ((size_t)b * CH + oa + 8) * HW + n;
            float2 r1 = *(const float2*)(x + o1);
            float2 r2 = *(const float2*)(x + o2);
            *(float2*)(out + o1) = make_float2(c[0] + ba + r1.x, c[1] + ba + r1.y);
            *(float2*)(out + o2) = make_float2(c[2] + bb + r2.x, c[3] + bb + r2.y);
        }
    }
}

// ---------------- host ----------------
#define SMEM_BIG  ((128 * RB + 256 * RB) * 3)          // 92160 (covers 256x136 half staging)
#define SMEM_SM   ((128 * RB + 128 * RB) * 3)          // 61440
#define SMEM_QKS  66560                                // 128x130 fp32 softmax staging

extern "C" void kernel_launch(void* const* d_in, const int* in_sizes, int n_in,
                              void* d_out, int out_size) {
    const float* x      = (const float*)d_in[0];
    const float* gn_w   = (const float*)d_in[1];
    const float* gn_b   = (const float*)d_in[2];
    const float* qkv_w  = (const float*)d_in[3];
    const float* qkv_b  = (const float*)d_in[4];
    const float* proj_w = (const float*)d_in[5];
    const float* proj_b = (const float*)d_in[6];
    float* out = (float*)d_out;

    cudaFuncSetAttribute(k_qkv,  cudaFuncAttributeMaxDynamicSharedMemorySize, SMEM_BIG);
    cudaFuncSetAttribute(k_proj, cudaFuncAttributeMaxDynamicSharedMemorySize, SMEM_BIG);
    cudaFuncSetAttribute(k_qks,  cudaFuncAttributeMaxDynamicSharedMemorySize, SMEM_QKS);
    cudaFuncSetAttribute(k_av,   cudaFuncAttributeMaxDynamicSharedMemorySize, SMEM_SM);

    gn_stats<<<BATCH * NG, 256>>>(x);
    gn_apply_T<<<dim3(HW / 32, CH / 32, BATCH), dim3(32, 8)>>>(x, gn_w, gn_b);
    conv_w<<<(4 * CH * CH) / 256, 256>>>(qkv_w, proj_w);

    k_qkv <<<dim3(HW / 256, 12, BATCH), 256, SMEM_BIG>>>(qkv_b);
    k_qks <<<BATCH * HEADS, 256, SMEM_QKS>>>();
    k_av  <<<dim3(HW / 128, 1, BATCH * HEADS), 256, SMEM_SM>>>();
    k_proj<<<dim3(HW / 256, CH / 128, BATCH), 256, SMEM_BIG>>>(proj_b, x, out);

    (void)in_sizes; (void)n_in; (void)out_size;
}

// round 11
// speedup vs baseline: 5.0781x; 1.3116x over previous
#include <cuda_runtime.h>
#include <cuda_fp16.h>
#include <cstdint>

#define BATCH  8
#define CH     512
#define HW     4096
#define HEADS  4
#define DH     128
#define NG     32
#define EPS    1e-5f
#define NCHUNK 8

// ---------------- scratch (device globals; allocation-free) ----------------
__device__ __align__(1024) __half g_hnT[(size_t)BATCH * HW * CH];   // [b][n][c]
__device__ __align__(1024) __half g_qk [(size_t)BATCH * 1024 * HW]; // [b][o<1024][n] q,k
__device__ __align__(1024) __half g_vT [(size_t)BATCH * HW * CH];   // [b][n][e]
__device__ __align__(1024) __half g_at [(size_t)BATCH * HEADS * DH * DH]; // [bh][d][e]
__device__ __align__(1024) __half g_aoT[(size_t)BATCH * HW * CH];   // [b][n][c]
__device__ __align__(1024) __half g_w16[(size_t)4 * CH * CH];       // qkv_w then proj_w
__device__ __align__(1024) float  g_Sp [(size_t)BATCH * HEADS * NCHUNK * DH * DH]; // 16MB partials
__device__ float g_mean[BATCH * NG], g_rstd[BATCH * NG];

// ---------------- helpers ----------------
__device__ __forceinline__ uint32_t smem_u32(const void* p) {
    uint32_t a;
    asm("{ .reg .u64 t; cvta.to.shared.u64 t, %1; cvt.u32.u64 %0, t; }" : "=r"(a) : "l"(p));
    return a;
}
#define CPA16(sa, gp) \
    asm volatile("cp.async.cg.shared.global [%0], [%1], 16;" :: "r"(sa), "l"(gp))
#define CP_COMMIT() asm volatile("cp.async.commit_group;" ::: "memory")
#define CP_WAIT(n)  asm volatile("cp.async.wait_group %0;" :: "n"(n) : "memory")

// SMEM tile rows: 32 halves (64B) payload, padded row stride 80B (conflict-free ldmatrix)
#define RB 80

__device__ __forceinline__ void load_tile128(uint32_t sb, const __half* __restrict__ g,
                                             size_t stride, int tid) {
    #pragma unroll
    for (int i = 0; i < 2; i++) {
        int idx = tid + i * 256, row = idx >> 2, ch = idx & 3;
        CPA16(sb + row * RB + ch * 16, g + (size_t)row * stride + ch * 8);
    }
}

// Block GEMM: D[128 m][128 n] = A[128,K] x B[128,K], both K-major. 256 thr, 8 warps (2m x 4n),
// warp tile 64x32, fp32 accum acc[(mf*4+nf)*4+e]. 3-stage cp.async pipeline.
// No trailing barrier — callers __syncthreads() before reusing smem.
__device__ __forceinline__ void hgemm_block(const __half* __restrict__ A, size_t sA,
                                            const __half* __restrict__ B, size_t sB,
                                            int K, char* sm, float* acc) {
    constexpr int ABYTES = 128 * RB;
    constexpr int STAGE  = 2 * ABYTES;
    uint32_t s0 = smem_u32(sm);
    int tid = threadIdx.x, lane = tid & 31, w = tid >> 5;
    int wm = w & 1, wn = w >> 1;

    #pragma unroll
    for (int i = 0; i < 64; i++) acc[i] = 0.f;

    const int S = K >> 5;
    load_tile128(s0, A, sA, tid);
    load_tile128(s0 + ABYTES, B, sB, tid);
    CP_COMMIT();
    if (S > 1) {
        load_tile128(s0 + STAGE, A + 32, sA, tid);
        load_tile128(s0 + STAGE + ABYTES, B + 32, sB, tid);
        CP_COMMIT();
    }

    int slot_c = 0, slot_p = 2;
    for (int s = 0; s < S; s++) {
        if (s + 1 < S) CP_WAIT(1); else CP_WAIT(0);
        __syncthreads();
        if (s + 2 < S) {
            load_tile128(s0 + slot_p * STAGE, A + (size_t)(s + 2) * 32, sA, tid);
            load_tile128(s0 + slot_p * STAGE + ABYTES, B + (size_t)(s + 2) * 32, sB, tid);
            CP_COMMIT();
        }
        uint32_t Ab = s0 + slot_c * STAGE;
        uint32_t Bb = Ab + ABYTES;
        slot_c = (slot_c + 1 == 3) ? 0 : slot_c + 1;
        slot_p = (slot_p + 1 == 3) ? 0 : slot_p + 1;

        #pragma unroll
        for (int kk = 0; kk < 2; kk++) {
            uint32_t af[4][4], bf[4][2];
            #pragma unroll
            for (int mf = 0; mf < 4; mf++) {
                int r  = wm * 64 + mf * 16 + (lane & 7) + ((lane >> 3) & 1) * 8;
                int cb = kk * 32 + (lane >> 4) * 16;
                asm volatile("ldmatrix.sync.aligned.m8n8.x4.shared.b16 {%0,%1,%2,%3}, [%4];"
                    : "=r"(af[mf][0]), "=r"(af[mf][1]), "=r"(af[mf][2]), "=r"(af[mf][3])
                    : "r"(Ab + r * RB + cb));
            }
            #pragma unroll
            for (int p = 0; p < 2; p++) {
                int r  = wn * 32 + p * 16 + (lane >> 4) * 8 + (lane & 7);
                int cb = kk * 32 + ((lane >> 3) & 1) * 16;
                asm volatile("ldmatrix.sync.aligned.m8n8.x4.shared.b16 {%0,%1,%2,%3}, [%4];"
                    : "=r"(bf[2 * p][0]), "=r"(bf[2 * p][1]),
                      "=r"(bf[2 * p + 1][0]), "=r"(bf[2 * p + 1][1])
                    : "r"(Bb + r * RB + cb));
            }
            #pragma unroll
            for (int mf = 0; mf < 4; mf++)
                #pragma unroll
                for (int nf = 0; nf < 4; nf++) {
                    float* c = acc + (mf * 4 + nf) * 4;
                    asm volatile(
                        "mma.sync.aligned.m16n8k16.row.col.f32.f16.f16.f32 "
                        "{%0,%1,%2,%3}, {%4,%5,%6,%7}, {%8,%9}, {%0,%1,%2,%3};"
                        : "+f"(c[0]), "+f"(c[1]), "+f"(c[2]), "+f"(c[3])
                        : "r"(af[mf][0]), "r"(af[mf][1]), "r"(af[mf][2]), "r"(af[mf][3]),
                          "r"(bf[nf][0]), "r"(bf[nf][1]));
                }
        }
    }
}

// ---------------- GroupNorm ----------------
#define GSZ (CH / NG * HW)
__global__ __launch_bounds__(256) void gn_stats(const float* __restrict__ x) {
    int bg = blockIdx.x;
    const float4* p = (const float4*)(x + (size_t)bg * GSZ);
    float s = 0.f, sq = 0.f;
    for (int i = threadIdx.x; i < GSZ / 4; i += 256) {
        float4 v = p[i];
        s  += v.x + v.y + v.z + v.w;
        sq += v.x * v.x + v.y * v.y + v.z * v.z + v.w * v.w;
    }
    __shared__ float ss[8], sr[8];
    #pragma unroll
    for (int o = 16; o; o >>= 1) { s += __shfl_down_sync(~0u, s, o); sq += __shfl_down_sync(~0u, sq, o); }
    int w = threadIdx.x >> 5, l = threadIdx.x & 31;
    if (l == 0) { ss[w] = s; sr[w] = sq; }
    __syncthreads();
    if (w == 0) {
        s  = (l < 8) ? ss[l] : 0.f;
        sq = (l < 8) ? sr[l] : 0.f;
        #pragma unroll
        for (int o = 4; o; o >>= 1) { s += __shfl_down_sync(~0u, s, o); sq += __shfl_down_sync(~0u, sq, o); }
        if (l == 0) {
            float mu = s * (1.f / GSZ);
            float va = sq * (1.f / GSZ) - mu * mu;
            g_mean[bg] = mu;
            g_rstd[bg] = rsqrtf(va + EPS);
        }
    }
}

__global__ __launch_bounds__(256) void gn_apply_T(const float* __restrict__ x,
                                                  const float* __restrict__ gw,
                                                  const float* __restrict__ gb) {
    __shared__ float t[32][33];
    int b = blockIdx.z, c0 = blockIdx.y * 32, n0 = blockIdx.x * 32;
    int tx = threadIdx.x, ty = threadIdx.y;   // 32 x 8
    #pragma unroll
    for (int i = 0; i < 4; i++) {
        int c  = c0 + ty + i * 8;
        int bg = b * NG + (c >> 4);
        float r = g_rstd[bg];
        float w = gw[c] * r;
        float bb = gb[c] - g_mean[bg] * w;
        t[ty + i * 8][tx] = x[((size_t)b * CH + c) * HW + n0 + tx] * w + bb;
    }
    __syncthreads();
    #pragma unroll
    for (int i = 0; i < 4; i++) {
        int n = n0 + ty + i * 8;
        g_hnT[((size_t)b * HW + n) * CH + c0 + tx] = __float2half_rn(t[tx][ty + i * 8]);
    }
}

__global__ __launch_bounds__(256) void conv_w(const float* __restrict__ qw,
                                              const float* __restrict__ pw) {
    int i = blockIdx.x * 256 + threadIdx.x;
    const int NQ = 3 * CH * CH;
    float v = (i < NQ) ? qw[i] : pw[i - NQ];
    g_w16[i] = __float2half_rn(v);
}

// ---------------- QKV: D[o][n] = qkv_w x hn ----------------
__global__ __launch_bounds__(256, 2) void k_qkv(const float* __restrict__ qkv_b) {
    extern __shared__ char sm[];
    int n0 = blockIdx.x * 128, o0 = blockIdx.y * 128, b = blockIdx.z;
    float acc[64];
    hgemm_block(g_w16 + (size_t)o0 * CH, CH,
                g_hnT + ((size_t)b * HW + n0) * CH, CH, CH, sm, acc);

    int tid = threadIdx.x, lane = tid & 31, w = tid >> 5;
    int wm = w & 1, wn = w >> 1, g = lane >> 2, ti = lane & 3;

    if (o0 < 1024) {   // q,k: coalesced direct [o][n] stores
        #pragma unroll
        for (int mf = 0; mf < 4; mf++) {
            int oa = o0 + wm * 64 + mf * 16 + g;
            float ba = qkv_b[oa], bb = qkv_b[oa + 8];
            #pragma unroll
            for (int nf = 0; nf < 4; nf++) {
                int n = n0 + wn * 32 + nf * 8 + ti * 2;
                float* c = acc + (mf * 4 + nf) * 4;
                *(__half2*)(g_qk + ((size_t)(b * 1024 + oa)) * HW + n) =
                    __floats2half2_rn(c[0] + ba, c[1] + ba);
                *(__half2*)(g_qk + ((size_t)(b * 1024 + oa + 8)) * HW + n) =
                    __floats2half2_rn(c[2] + bb, c[3] + bb);
            }
        }
    } else {           // v: transpose via SMEM -> vT[n][e]
        __syncthreads();
        __half* Ts = (__half*)sm;   // [128 n][136]
        #pragma unroll
        for (int mf = 0; mf < 4; mf++) {
            int ol = wm * 64 + mf * 16 + g;
            float ba = qkv_b[o0 + ol], bb = qkv_b[o0 + ol + 8];
            #pragma unroll
            for (int nf = 0; nf < 4; nf++) {
                int nl = wn * 32 + nf * 8 + ti * 2;
                float* c = acc + (mf * 4 + nf) * 4;
                Ts[(nl    ) * 136 + ol    ] = __float2half_rn(c[0] + ba);
                Ts[(nl + 1) * 136 + ol    ] = __float2half_rn(c[1] + ba);
                Ts[(nl    ) * 136 + ol + 8] = __float2half_rn(c[2] + bb);
                Ts[(nl + 1) * 136 + ol + 8] = __float2half_rn(c[3] + bb);
            }
        }
        __syncthreads();
        int r = tid >> 1, part = tid & 1;
        uint4* dst = (uint4*)(g_vT + ((size_t)b * HW + n0 + r) * CH + (o0 - 1024) + part * 64);
        const uint4* src = (const uint4*)(Ts + r * 136 + part * 64);
        #pragma unroll
        for (int j = 0; j < 8; j++) dst[j] = src[j];
    }
}

// ---------------- QK^T split-K partials: Sp[bh][chunk] = q_chunk x k_chunk^T ----------------
__global__ __launch_bounds__(256, 2) void qk_part() {
    extern __shared__ char sm[];
    int chunk = blockIdx.x, bh = blockIdx.y, b = bh >> 2, h = bh & 3;
    const __half* A = g_qk + ((size_t)(b * 1024 + h * DH)) * HW + chunk * (HW / NCHUNK);
    const __half* B = g_qk + ((size_t)(b * 1024 + 512 + h * DH)) * HW + chunk * (HW / NCHUNK);
    float acc[64];
    hgemm_block(A, HW, B, HW, HW / NCHUNK, sm, acc);

    float* Sp = g_Sp + ((size_t)bh * NCHUNK + chunk) * DH * DH;
    int lane = threadIdx.x & 31, w = threadIdx.x >> 5;
    int wm = w & 1, wn = w >> 1, g = lane >> 2, ti = lane & 3;
    #pragma unroll
    for (int mf = 0; mf < 4; mf++) {
        int ml = wm * 64 + mf * 16 + g;
        #pragma unroll
        for (int nf = 0; nf < 4; nf++) {
            int nl = wn * 32 + nf * 8 + ti * 2;
            float* c = acc + (mf * 4 + nf) * 4;
            *(float2*)(Sp + (size_t)ml * DH + nl)       = make_float2(c[0], c[1]);
            *(float2*)(Sp + (size_t)(ml + 8) * DH + nl) = make_float2(c[2], c[3]);
        }
    }
}

// ---------------- reduce partials + scale + softmax -> g_at fp16 ----------------
__global__ __launch_bounds__(128) void k_softmax() {
    int row = blockIdx.x, bh = blockIdx.y, t = threadIdx.x;
    const float* Sp = g_Sp + (size_t)bh * NCHUNK * DH * DH + (size_t)row * DH + t;
    float v = 0.f;
    #pragma unroll
    for (int c = 0; c < NCHUNK; c++) v += Sp[(size_t)c * DH * DH];
    v *= 0.08838834764831845f;   // 128^-0.5

    __shared__ float red[4];
    int w = t >> 5, l = t & 31;
    float m = v;
    #pragma unroll
    for (int o = 16; o; o >>= 1) m = fmaxf(m, __shfl_xor_sync(~0u, m, o));
    if (l == 0) red[w] = m;
    __syncthreads();
    m = fmaxf(fmaxf(red[0], red[1]), fmaxf(red[2], red[3]));
    __syncthreads();
    float e = __expf(v - m), su = e;
    #pragma unroll
    for (int o = 16; o; o >>= 1) su += __shfl_xor_sync(~0u, su, o);
    if (l == 0) red[w] = su;
    __syncthreads();
    su = red[0] + red[1] + red[2] + red[3];
    g_at[((size_t)bh * DH + row) * DH + t] = __float2half_rn(e / su);
}

// ---------------- AV: ao[d][n] -> aoT[n][c] ----------------
__global__ __launch_bounds__(256, 2) void k_av() {
    extern __shared__ char sm[];
    int n0 = blockIdx.x * 128, bh = blockIdx.z, b = bh >> 2, h = bh & 3;
    float acc[64];
    hgemm_block(g_at + (size_t)bh * DH * DH, DH,
                g_vT + ((size_t)b * HW + n0) * CH + h * DH, CH, DH, sm, acc);
    __syncthreads();

    __half* Ts = (__half*)sm;   // [128 n][136]
    int tid = threadIdx.x, lane = tid & 31, w = tid >> 5;
    int wm = w & 1, wn = w >> 1, g = lane >> 2, ti = lane & 3;
    #pragma unroll
    for (int mf = 0; mf < 4; mf++) {
        int dl = wm * 64 + mf * 16 + g;
        #pragma unroll
        for (int nf = 0; nf < 4; nf++) {
            int nl = wn * 32 + nf * 8 + ti * 2;
            float* c = acc + (mf * 4 + nf) * 4;
            Ts[(nl    ) * 136 + dl    ] = __float2half_rn(c[0]);
            Ts[(nl + 1) * 136 + dl    ] = __float2half_rn(c[1]);
            Ts[(nl    ) * 136 + dl + 8] = __float2half_rn(c[2]);
            Ts[(nl + 1) * 136 + dl + 8] = __float2half_rn(c[3]);
        }
    }
    __syncthreads();
    int r = tid >> 1, part = tid & 1;
    uint4* dst = (uint4*)(g_aoT + ((size_t)b * HW + n0 + r) * CH + h * DH + part * 64);
    const uint4* src = (const uint4*)(Ts + r * 136 + part * 64);
    #pragma unroll
    for (int j = 0; j < 8; j++) dst[j] = src[j];
}

// ---------------- proj + bias + residual ----------------
__global__ __launch_bounds__(256, 2) void k_proj(const float* __restrict__ proj_b,
                                                 const float* __restrict__ x,
                                                 float* __restrict__ out) {
    extern __shared__ char sm[];
    int n0 = blockIdx.x * 128, o0 = blockIdx.y * 128, b = blockIdx.z;
    float acc[64];
    hgemm_block(g_w16 + (size_t)3 * CH * CH + (size_t)o0 * CH, CH,
                g_aoT + ((size_t)b * HW + n0) * CH, CH, CH, sm, acc);

    int tid = threadIdx.x, lane = tid & 31, w = tid >> 5;
    int wm = w & 1, wn = w >> 1, g = lane >> 2, ti = lane & 3;
    #pragma unroll
    for (int mf = 0; mf < 4; mf++) {
        int oa = o0 + wm * 64 + mf * 16 + g;
        float ba = proj_b[oa], bb = proj_b[oa + 8];
        #pragma unroll
        for (int nf = 0; nf < 4; nf++) {
            int n = n0 + wn * 32 + nf * 8 + ti * 2;
            float* c = acc + (mf * 4 + nf) * 4;
            size_t o1 = ((size_t)b * CH + oa) * HW + n;
            size_t o2 = ((size_t)b * CH + oa + 8) * HW + n;
            float2 r1 = *(const float2*)(x + o1);
            float2 r2 = *(const float2*)(x + o2);
            *(float2*)(out + o1) = make_float2(c[0] + ba + r1.x, c[1] + ba + r1.y);
            *(float2*)(out + o2) = make_float2(c[2] + bb + r2.x, c[3] + bb + r2.y);
        }
    }
}

// ---------------- host ----------------
#define SMEM_G ((128 * RB + 128 * RB) * 3)   // 61440; x2 CTAs = 120KB/SM

extern "C" void kernel_launch(void* const* d_in, const int* in_sizes, int n_in,
                              void* d_out, int out_size) {
    const float* x      = (const float*)d_in[0];
    const float* gn_w   = (const float*)d_in[1];
    const float* gn_b   = (const float*)d_in[2];
    const float* qkv_w  = (const float*)d_in[3];
    const float* qkv_b  = (const float*)d_in[4];
    const float* proj_w = (const float*)d_in[5];
    const float* proj_b = (const float*)d_in[6];
    float* out = (float*)d_out;

    cudaFuncSetAttribute(k_qkv,   cudaFuncAttributeMaxDynamicSharedMemorySize, SMEM_G);
    cudaFuncSetAttribute(qk_part, cudaFuncAttributeMaxDynamicSharedMemorySize, SMEM_G);
    cudaFuncSetAttribute(k_av,    cudaFuncAttributeMaxDynamicSharedMemorySize, SMEM_G);
    cudaFuncSetAttribute(k_proj,  cudaFuncAttributeMaxDynamicSharedMemorySize, SMEM_G);

    gn_stats<<<BATCH * NG, 256>>>(x);
    gn_apply_T<<<dim3(HW / 32, CH / 32, BATCH), dim3(32, 8)>>>(x, gn_w, gn_b);
    conv_w<<<(4 * CH * CH) / 256, 256>>>(qkv_w, proj_w);

    k_qkv  <<<dim3(HW / 128, 12, BATCH), 256, SMEM_G>>>(qkv_b);
    qk_part<<<dim3(NCHUNK, BATCH * HEADS), 256, SMEM_G>>>();
    k_softmax<<<dim3(DH, BATCH * HEADS), 128>>>();
    k_av   <<<dim3(HW / 128, 1, BATCH * HEADS), 256, SMEM_G>>>();
    k_proj <<<dim3(HW / 128, CH / 128, BATCH), 256, SMEM_G>>>(proj_b, x, out);

    (void)in_sizes; (void)n_in; (void)out_size;
}

// round 13
// speedup vs baseline: 5.4502x; 1.0733x over previous
#include <cuda_runtime.h>
#include <cuda_fp16.h>
#include <cstdint>

#define BATCH  8
#define CH     512
#define HW     4096
#define HEADS  4
#define DH     128
#define NG     32
#define EPS    1e-5f
#define NCHUNK 8

// ---------------- scratch (device globals; allocation-free) ----------------
__device__ __align__(1024) __half g_hnT[(size_t)BATCH * HW * CH];   // [b][n][c]
__device__ __align__(1024) __half g_qk [(size_t)BATCH * 1024 * HW]; // [b][o<1024][n] q,k
__device__ __align__(1024) __half g_vT [(size_t)BATCH * HW * CH];   // [b][n][e]
__device__ __align__(1024) __half g_at [(size_t)BATCH * HEADS * DH * DH]; // [bh][d][e]
__device__ __align__(1024) __half g_aoT[(size_t)BATCH * HW * CH];   // [b][n][c]
__device__ __align__(1024) __half g_w16[(size_t)4 * CH * CH];       // qkv_w then proj_w
__device__ __align__(1024) float  g_Sp [(size_t)BATCH * HEADS * NCHUNK * DH * DH]; // 16MB partials
__device__ float g_mean[BATCH * NG], g_rstd[BATCH * NG];

// ---------------- helpers ----------------
__device__ __forceinline__ uint32_t smem_u32(const void* p) {
    uint32_t a;
    asm("{ .reg .u64 t; cvta.to.shared.u64 t, %1; cvt.u32.u64 %0, t; }" : "=r"(a) : "l"(p));
    return a;
}
#define CPA16(sa, gp) \
    asm volatile("cp.async.cg.shared.global [%0], [%1], 16;" :: "r"(sa), "l"(gp))
#define CP_COMMIT() asm volatile("cp.async.commit_group;" ::: "memory")
#define CP_WAIT(n)  asm volatile("cp.async.wait_group %0;" :: "n"(n) : "memory")

// SMEM tile rows: 64 halves (128B) payload, padded row stride 144B.
// Conflict-free for ldmatrix (8 rows -> disjoint bank groups) and for
// cp.async stores (start bank = 4*(9r+c mod 8) per warp, distinct phases).
#define RB 144

// 128 rows x 128B payload (one 64-K slab of a 128-row operand)
__device__ __forceinline__ void load_tile128(uint32_t sb, const __half* __restrict__ g,
                                             size_t stride, int tid) {
    #pragma unroll
    for (int i = 0; i < 4; i++) {
        int idx = tid + i * 256, row = idx >> 3, ch = idx & 7;
        CPA16(sb + row * RB + ch * 16, g + (size_t)row * stride + ch * 8);
    }
}

// Block GEMM: D[128 m][128 n] = A[128,K] x B[128,K], both K-major. 256 thr, 8 warps (2m x 4n),
// warp tile 64x32, fp32 accum acc[(mf*4+nf)*4+e]. 3-stage cp.async pipeline, 64-K slabs,
// ONE __syncthreads per slab. No trailing barrier — callers barrier before reusing smem.
__device__ __forceinline__ void hgemm_block(const __half* __restrict__ A, size_t sA,
                                            const __half* __restrict__ B, size_t sB,
                                            int K, char* sm, float* acc) {
    constexpr int ABYTES = 128 * RB;      // 18432
    constexpr int STAGE  = 2 * ABYTES;    // 36864
    uint32_t s0 = smem_u32(sm);
    int tid = threadIdx.x, lane = tid & 31, w = tid >> 5;
    int wm = w & 1, wn = w >> 1;

    #pragma unroll
    for (int i = 0; i < 64; i++) acc[i] = 0.f;

    const int S = K >> 6;                 // 64-K slabs
    load_tile128(s0, A, sA, tid);
    load_tile128(s0 + ABYTES, B, sB, tid);
    CP_COMMIT();
    if (S > 1) {
        load_tile128(s0 + STAGE, A + 64, sA, tid);
        load_tile128(s0 + STAGE + ABYTES, B + 64, sB, tid);
        CP_COMMIT();
    }

    int slot_c = 0, slot_p = 2;
    for (int s = 0; s < S; s++) {
        if (s + 1 < S) CP_WAIT(1); else CP_WAIT(0);
        __syncthreads();
        if (s + 2 < S) {
            load_tile128(s0 + slot_p * STAGE, A + (size_t)(s + 2) * 64, sA, tid);
            load_tile128(s0 + slot_p * STAGE + ABYTES, B + (size_t)(s + 2) * 64, sB, tid);
            CP_COMMIT();
        }
        uint32_t Ab = s0 + slot_c * STAGE;
        uint32_t Bb = Ab + ABYTES;
        slot_c = (slot_c + 1 == 3) ? 0 : slot_c + 1;
        slot_p = (slot_p + 1 == 3) ? 0 : slot_p + 1;

        #pragma unroll
        for (int kk = 0; kk < 4; kk++) {
            uint32_t af[4][4], bf[4][2];
            #pragma unroll
            for (int mf = 0; mf < 4; mf++) {
                int r  = wm * 64 + mf * 16 + (lane & 7) + ((lane >> 3) & 1) * 8;
                int cb = kk * 32 + (lane >> 4) * 16;
                asm volatile("ldmatrix.sync.aligned.m8n8.x4.shared.b16 {%0,%1,%2,%3}, [%4];"
                    : "=r"(af[mf][0]), "=r"(af[mf][1]), "=r"(af[mf][2]), "=r"(af[mf][3])
                    : "r"(Ab + r * RB + cb));
            }
            #pragma unroll
            for (int p = 0; p < 2; p++) {
                int r  = wn * 32 + p * 16 + (lane >> 4) * 8 + (lane & 7);
                int cb = kk * 32 + ((lane >> 3) & 1) * 16;
                asm volatile("ldmatrix.sync.aligned.m8n8.x4.shared.b16 {%0,%1,%2,%3}, [%4];"
                    : "=r"(bf[2 * p][0]), "=r"(bf[2 * p][1]),
                      "=r"(bf[2 * p + 1][0]), "=r"(bf[2 * p + 1][1])
                    : "r"(Bb + r * RB + cb));
            }
            #pragma unroll
            for (int mf = 0; mf < 4; mf++)
                #pragma unroll
                for (int nf = 0; nf < 4; nf++) {
                    float* c = acc + (mf * 4 + nf) * 4;
                    asm volatile(
                        "mma.sync.aligned.m16n8k16.row.col.f32.f16.f16.f32 "
                        "{%0,%1,%2,%3}, {%4,%5,%6,%7}, {%8,%9}, {%0,%1,%2,%3};"
                        : "+f"(c[0]), "+f"(c[1]), "+f"(c[2]), "+f"(c[3])
                        : "r"(af[mf][0]), "r"(af[mf][1]), "r"(af[mf][2]), "r"(af[mf][3]),
                          "r"(bf[nf][0]), "r"(bf[nf][1]));
                }
        }
    }
}

// ---------------- GroupNorm ----------------
#define GSZ (CH / NG * HW)
__global__ __launch_bounds__(256) void gn_stats(const float* __restrict__ x) {
    int bg = blockIdx.x;
    const float4* p = (const float4*)(x + (size_t)bg * GSZ);
    float s = 0.f, sq = 0.f;
    for (int i = threadIdx.x; i < GSZ / 4; i += 256) {
        float4 v = p[i];
        s  += v.x + v.y + v.z + v.w;
        sq += v.x * v.x + v.y * v.y + v.z * v.z + v.w * v.w;
    }
    __shared__ float ss[8], sr[8];
    #pragma unroll
    for (int o = 16; o; o >>= 1) { s += __shfl_down_sync(~0u, s, o); sq += __shfl_down_sync(~0u, sq, o); }
    int w = threadIdx.x >> 5, l = threadIdx.x & 31;
    if (l == 0) { ss[w] = s; sr[w] = sq; }
    __syncthreads();
    if (w == 0) {
        s  = (l < 8) ? ss[l] : 0.f;
        sq = (l < 8) ? sr[l] : 0.f;
        #pragma unroll
        for (int o = 4; o; o >>= 1) { s += __shfl_down_sync(~0u, s, o); sq += __shfl_down_sync(~0u, sq, o); }
        if (l == 0) {
            float mu = s * (1.f / GSZ);
            float va = sq * (1.f / GSZ) - mu * mu;
            g_mean[bg] = mu;
            g_rstd[bg] = rsqrtf(va + EPS);
        }
    }
}

__global__ __launch_bounds__(256) void gn_apply_T(const float* __restrict__ x,
                                                  const float* __restrict__ gw,
                                                  const float* __restrict__ gb) {
    __shared__ float t[32][33];
    int b = blockIdx.z, c0 = blockIdx.y * 32, n0 = blockIdx.x * 32;
    int tx = threadIdx.x, ty = threadIdx.y;   // 32 x 8
    #pragma unroll
    for (int i = 0; i < 4; i++) {
        int c  = c0 + ty + i * 8;
        int bg = b * NG + (c >> 4);
        float r = g_rstd[bg];
        float w = gw[c] * r;
        float bb = gb[c] - g_mean[bg] * w;
        t[ty + i * 8][tx] = x[((size_t)b * CH + c) * HW + n0 + tx] * w + bb;
    }
    __syncthreads();
    #pragma unroll
    for (int i = 0; i < 4; i++) {
        int n = n0 + ty + i * 8;
        g_hnT[((size_t)b * HW + n) * CH + c0 + tx] = __float2half_rn(t[tx][ty + i * 8]);
    }
}

__global__ __launch_bounds__(256) void conv_w(const float* __restrict__ qw,
                                              const float* __restrict__ pw) {
    int i = blockIdx.x * 256 + threadIdx.x;
    const int NQ = 3 * CH * CH;
    float v = (i < NQ) ? qw[i] : pw[i - NQ];
    g_w16[i] = __float2half_rn(v);
}

// ---------------- QKV: D[o][n] = qkv_w x hn ----------------
__global__ __launch_bounds__(256, 2) void k_qkv(const float* __restrict__ qkv_b) {
    extern __shared__ char sm[];
    int n0 = blockIdx.x * 128, o0 = blockIdx.y * 128, b = blockIdx.z;
    float acc[64];
    hgemm_block(g_w16 + (size_t)o0 * CH, CH,
                g_hnT + ((size_t)b * HW + n0) * CH, CH, CH, sm, acc);

    int tid = threadIdx.x, lane = tid & 31, w = tid >> 5;
    int wm = w & 1, wn = w >> 1, g = lane >> 2, ti = lane & 3;

    if (o0 < 1024) {   // q,k: coalesced direct [o][n] stores
        #pragma unroll
        for (int mf = 0; mf < 4; mf++) {
            int oa = o0 + wm * 64 + mf * 16 + g;
            float ba = qkv_b[oa], bb = qkv_b[oa + 8];
            #pragma unroll
            for (int nf = 0; nf < 4; nf++) {
                int n = n0 + wn * 32 + nf * 8 + ti * 2;
                float* c = acc + (mf * 4 + nf) * 4;
                *(__half2*)(g_qk + ((size_t)(b * 1024 + oa)) * HW + n) =
                    __floats2half2_rn(c[0] + ba, c[1] + ba);
                *(__half2*)(g_qk + ((size_t)(b * 1024 + oa + 8)) * HW + n) =
                    __floats2half2_rn(c[2] + bb, c[3] + bb);
            }
        }
    } else {           // v: transpose via SMEM -> vT[n][e]
        __syncthreads();
        __half* Ts = (__half*)sm;   // [128 n][136]
        #pragma unroll
        for (int mf = 0; mf < 4; mf++) {
            int ol = wm * 64 + mf * 16 + g;
            float ba = qkv_b[o0 + ol], bb = qkv_b[o0 + ol + 8];
            #pragma unroll
            for (int nf = 0; nf < 4; nf++) {
                int nl = wn * 32 + nf * 8 + ti * 2;
                float* c = acc + (mf * 4 + nf) * 4;
                Ts[(nl    ) * 136 + ol    ] = __float2half_rn(c[0] + ba);
                Ts[(nl + 1) * 136 + ol    ] = __float2half_rn(c[1] + ba);
                Ts[(nl    ) * 136 + ol + 8] = __float2half_rn(c[2] + bb);
                Ts[(nl + 1) * 136 + ol + 8] = __float2half_rn(c[3] + bb);
            }
        }
        __syncthreads();
        int r = tid >> 1, part = tid & 1;
        uint4* dst = (uint4*)(g_vT + ((size_t)b * HW + n0 + r) * CH + (o0 - 1024) + part * 64);
        const uint4* src = (const uint4*)(Ts + r * 136 + part * 64);
        #pragma unroll
        for (int j = 0; j < 8; j++) dst[j] = src[j];
    }
}

// ---------------- QK^T split-K partials: Sp[bh][chunk] = q_chunk x k_chunk^T ----------------
__global__ __launch_bounds__(256, 2) void qk_part() {
    extern __shared__ char sm[];
    int chunk = blockIdx.x, bh = blockIdx.y, b = bh >> 2, h = bh & 3;
    const __half* A = g_qk + ((size_t)(b * 1024 + h * DH)) * HW + chunk * (HW / NCHUNK);
    const __half* B = g_qk + ((size_t)(b * 1024 + 512 + h * DH)) * HW + chunk * (HW / NCHUNK);
    float acc[64];
    hgemm_block(A, HW, B, HW, HW / NCHUNK, sm, acc);

    float* Sp = g_Sp + ((size_t)bh * NCHUNK + chunk) * DH * DH;
    int lane = threadIdx.x & 31, w = threadIdx.x >> 5;
    int wm = w & 1, wn = w >> 1, g = lane >> 2, ti = lane & 3;
    #pragma unroll
    for (int mf = 0; mf < 4; mf++) {
        int ml = wm * 64 + mf * 16 + g;
        #pragma unroll
        for (int nf = 0; nf < 4; nf++) {
            int nl = wn * 32 + nf * 8 + ti * 2;
            float* c = acc + (mf * 4 + nf) * 4;
            *(float2*)(Sp + (size_t)ml * DH + nl)       = make_float2(c[0], c[1]);
            *(float2*)(Sp + (size_t)(ml + 8) * DH + nl) = make_float2(c[2], c[3]);
        }
    }
}

// ---------------- reduce partials + scale + softmax -> g_at fp16 ----------------
__global__ __launch_bounds__(128) void k_softmax() {
    int row = blockIdx.x, bh = blockIdx.y, t = threadIdx.x;
    const float* Sp = g_Sp + (size_t)bh * NCHUNK * DH * DH + (size_t)row * DH + t;
    float v = 0.f;
    #pragma unroll
    for (int c = 0; c < NCHUNK; c++) v += Sp[(size_t)c * DH * DH];
    v *= 0.08838834764831845f;   // 128^-0.5

    __shared__ float red[4];
    int w = t >> 5, l = t & 31;
    float m = v;
    #pragma unroll
    for (int o = 16; o; o >>= 1) m = fmaxf(m, __shfl_xor_sync(~0u, m, o));
    if (l == 0) red[w] = m;
    __syncthreads();
    m = fmaxf(fmaxf(red[0], red[1]), fmaxf(red[2], red[3]));
    __syncthreads();
    float e = __expf(v - m), su = e;
    #pragma unroll
    for (int o = 16; o; o >>= 1) su += __shfl_xor_sync(~0u, su, o);
    if (l == 0) red[w] = su;
    __syncthreads();
    su = red[0] + red[1] + red[2] + red[3];
    g_at[((size_t)bh * DH + row) * DH + t] = __float2half_rn(e / su);
}

// ---------------- AV: ao[d][n] -> aoT[n][c] ----------------
__global__ __launch_bounds__(256, 2) void k_av() {
    extern __shared__ char sm[];
    int n0 = blockIdx.x * 128, bh = blockIdx.z, b = bh >> 2, h = bh & 3;
    float acc[64];
    hgemm_block(g_at + (size_t)bh * DH * DH, DH,
                g_vT + ((size_t)b * HW + n0) * CH + h * DH, CH, DH, sm, acc);
    __syncthreads();

    __half* Ts = (__half*)sm;   // [128 n][136]
    int tid = threadIdx.x, lane = tid & 31, w = tid >> 5;
    int wm = w & 1, wn = w >> 1, g = lane >> 2, ti = lane & 3;
    #pragma unroll
    for (int mf = 0; mf < 4; mf++) {
        int dl = wm * 64 + mf * 16 + g;
        #pragma unroll
        for (int nf = 0; nf < 4; nf++) {
            int nl = wn * 32 + nf * 8 + ti * 2;
            float* c = acc + (mf * 4 + nf) * 4;
            Ts[(nl    ) * 136 + dl    ] = __float2half_rn(c[0]);
            Ts[(nl + 1) * 136 + dl    ] = __float2half_rn(c[1]);
            Ts[(nl    ) * 136 + dl + 8] = __float2half_rn(c[2]);
            Ts[(nl + 1) * 136 + dl + 8] = __float2half_rn(c[3]);
        }
    }
    __syncthreads();
    int r = tid >> 1, part = tid & 1;
    uint4* dst = (uint4*)(g_aoT + ((size_t)b * HW + n0 + r) * CH + h * DH + part * 64);
    const uint4* src = (const uint4*)(Ts + r * 136 + part * 64);
    #pragma unroll
    for (int j = 0; j < 8; j++) dst[j] = src[j];
}

// ---------------- proj + bias + residual ----------------
__global__ __launch_bounds__(256, 2) void k_proj(const float* __restrict__ proj_b,
                                                 const float* __restrict__ x,
                                                 float* __restrict__ out) {
    extern __shared__ char sm[];
    int n0 = blockIdx.x * 128, o0 = blockIdx.y * 128, b = blockIdx.z;
    float acc[64];
    hgemm_block(g_w16 + (size_t)3 * CH * CH + (size_t)o0 * CH, CH,
                g_aoT + ((size_t)b * HW + n0) * CH, CH, CH, sm, acc);

    int tid = threadIdx.x, lane = tid & 31, w = tid >> 5;
    int wm = w & 1, wn = w >> 1, g = lane >> 2, ti = lane & 3;
    #pragma unroll
    for (int mf = 0; mf < 4; mf++) {
        int oa = o0 + wm * 64 + mf * 16 + g;
        float ba = proj_b[oa], bb = proj_b[oa + 8];
        #pragma unroll
        for (int nf = 0; nf < 4; nf++) {
            int n = n0 + wn * 32 + nf * 8 + ti * 2;
            float* c = acc + (mf * 4 + nf) * 4;
            size_t o1 = ((size_t)b * CH + oa) * HW + n;
            size_t o2 = ((size_t)b * CH + oa + 8) * HW + n;
            float2 r1 = *(const float2*)(x + o1);
            float2 r2 = *(const float2*)(x + o2);
            *(float2*)(out + o1) = make_float2(c[0] + ba + r1.x, c[1] + ba + r1.y);
            *(float2*)(out + o2) = make_float2(c[2] + bb + r2.x, c[3] + bb + r2.y);
        }
    }
}

// ---------------- host ----------------
#define SMEM_G (2 * 128 * RB * 3)   // 110592/CTA; x2 CTAs = 216KB/SM

extern "C" void kernel_launch(void* const* d_in, const int* in_sizes, int n_in,
                              void* d_out, int out_size) {
    const float* x      = (const float*)d_in[0];
    const float* gn_w   = (const float*)d_in[1];
    const float* gn_b   = (const float*)d_in[2];
    const float* qkv_w  = (const float*)d_in[3];
    const float* qkv_b  = (const float*)d_in[4];
    const float* proj_w = (const float*)d_in[5];
    const float* proj_b = (const float*)d_in[6];
    float* out = (float*)d_out;

    cudaFuncSetAttribute(k_qkv,   cudaFuncAttributeMaxDynamicSharedMemorySize, SMEM_G);
    cudaFuncSetAttribute(qk_part, cudaFuncAttributeMaxDynamicSharedMemorySize, SMEM_G);
    cudaFuncSetAttribute(k_av,    cudaFuncAttributeMaxDynamicSharedMemorySize, SMEM_G);
    cudaFuncSetAttribute(k_proj,  cudaFuncAttributeMaxDynamicSharedMemorySize, SMEM_G);

    gn_stats<<<BATCH * NG, 256>>>(x);
    gn_apply_T<<<dim3(HW / 32, CH / 32, BATCH), dim3(32, 8)>>>(x, gn_w, gn_b);
    conv_w<<<(4 * CH * CH) / 256, 256>>>(qkv_w, proj_w);

    k_qkv  <<<dim3(HW / 128, 12, BATCH), 256, SMEM_G>>>(qkv_b);
    qk_part<<<dim3(NCHUNK, BATCH * HEADS), 256, SMEM_G>>>();
    k_softmax<<<dim3(DH, BATCH * HEADS), 128>>>();
    k_av   <<<dim3(HW / 128, 1, BATCH * HEADS), 256, SMEM_G>>>();
    k_proj <<<dim3(HW / 128, CH / 128, BATCH), 256, SMEM_G>>>(proj_b, x, out);

    (void)in_sizes; (void)n_in; (void)out_size;
}

// round 14
// speedup vs baseline: 5.4914x; 1.0076x over previous
#include <cuda_runtime.h>
#include <cuda_fp16.h>
#include <cstdint>

#define BATCH  8
#define CH     512
#define HW     4096
#define HEADS  4
#define DH     128
#define NG     32
#define EPS    1e-5f
#define NCHUNK 8

// ---------------- scratch (device globals; allocation-free) ----------------
__device__ __align__(1024) __half g_hnT[(size_t)BATCH * HW * CH];   // [b][n][c]
__device__ __align__(1024) __half g_qk [(size_t)BATCH * 1024 * HW]; // [b][o<1024][n] q,k
__device__ __align__(1024) __half g_vT [(size_t)BATCH * HW * CH];   // [b][n][e]
__device__ __align__(1024) __half g_at [(size_t)BATCH * HEADS * DH * DH]; // [bh][d][e]
__device__ __align__(1024) __half g_aoT[(size_t)BATCH * HW * CH];   // [b][n][c]
__device__ __align__(1024) __half g_w16[(size_t)4 * CH * CH];       // qkv_w then proj_w
__device__ __align__(1024) float  g_Sp [(size_t)BATCH * HEADS * NCHUNK * DH * DH]; // 16MB partials
__device__ float g_mean[BATCH * NG], g_rstd[BATCH * NG];

// ---------------- helpers ----------------
__device__ __forceinline__ uint32_t smem_u32(const void* p) {
    uint32_t a;
    asm("{ .reg .u64 t; cvta.to.shared.u64 t, %1; cvt.u32.u64 %0, t; }" : "=r"(a) : "l"(p));
    return a;
}
#define CPA16(sa, gp) \
    asm volatile("cp.async.cg.shared.global [%0], [%1], 16;" :: "r"(sa), "l"(gp))
#define CP_COMMIT() asm volatile("cp.async.commit_group;" ::: "memory")
#define CP_WAIT(n)  asm volatile("cp.async.wait_group %0;" :: "n"(n) : "memory")

// SMEM tile rows: 64 halves (128B) payload, padded row stride 144B (conflict-free).
#define RB 144

// 128 rows x 128B payload (one 64-K slab of a 128-row operand)
__device__ __forceinline__ void load_tile128(uint32_t sb, const __half* __restrict__ g,
                                             size_t stride, int tid) {
    #pragma unroll
    for (int i = 0; i < 4; i++) {
        int idx = tid + i * 256, row = idx >> 3, ch = idx & 7;
        CPA16(sb + row * RB + ch * 16, g + (size_t)row * stride + ch * 8);
    }
}

#define LDSM_X4(d0, d1, d2, d3, addr) \
    asm volatile("ldmatrix.sync.aligned.m8n8.x4.shared.b16 {%0,%1,%2,%3}, [%4];" \
        : "=r"(d0), "=r"(d1), "=r"(d2), "=r"(d3) : "r"(addr))

// Block GEMM: D[128 m][128 n] = A[128,K] x B[128,K], both K-major. 256 thr, 8 warps (2m x 4n),
// warp tile 64x32, fp32 accum acc[(mf*4+nf)*4+e]. 3-stage cp.async pipeline, 64-K slabs,
// one __syncthreads per slab, and REGISTER double-buffered fragments across kk-steps so
// HMMAs never wait on same-iteration LDSM results. No trailing barrier.
__device__ __forceinline__ void hgemm_block(const __half* __restrict__ A, size_t sA,
                                            const __half* __restrict__ B, size_t sB,
                                            int K, char* sm, float* acc) {
    constexpr int ABYTES = 128 * RB;      // 18432
    constexpr int STAGE  = 2 * ABYTES;    // 36864
    uint32_t s0 = smem_u32(sm);
    int tid = threadIdx.x, lane = tid & 31, w = tid >> 5;
    int wm = w & 1, wn = w >> 1;

    // per-warp fragment base offsets (kk-invariant part of LDSM addresses)
    uint32_t aoff = (uint32_t)((wm * 64 + (lane & 7) + ((lane >> 3) & 1) * 8) * RB
                               + (lane >> 4) * 16);
    uint32_t boff = (uint32_t)((wn * 32 + (lane >> 4) * 8 + (lane & 7)) * RB
                               + ((lane >> 3) & 1) * 16);

    #pragma unroll
    for (int i = 0; i < 64; i++) acc[i] = 0.f;

    const int S = K >> 6;                 // 64-K slabs
    load_tile128(s0, A, sA, tid);
    load_tile128(s0 + ABYTES, B, sB, tid);
    CP_COMMIT();
    if (S > 1) {
        load_tile128(s0 + STAGE, A + 64, sA, tid);
        load_tile128(s0 + STAGE + ABYTES, B + 64, sB, tid);
        CP_COMMIT();
    }

    uint32_t af[2][4][4], bf[2][4][2];
    int slot_c = 0, slot_p = 2;
    for (int s = 0; s < S; s++) {
        if (s + 1 < S) CP_WAIT(1); else CP_WAIT(0);
        __syncthreads();
        if (s + 2 < S) {
            load_tile128(s0 + slot_p * STAGE, A + (size_t)(s + 2) * 64, sA, tid);
            load_tile128(s0 + slot_p * STAGE + ABYTES, B + (size_t)(s + 2) * 64, sB, tid);
            CP_COMMIT();
        }
        uint32_t Ab = s0 + slot_c * STAGE + aoff;
        uint32_t Bb = s0 + slot_c * STAGE + ABYTES + boff;
        slot_c = (slot_c + 1 == 3) ? 0 : slot_c + 1;
        slot_p = (slot_p + 1 == 3) ? 0 : slot_p + 1;

        // preload kk=0 fragments into buffer 0
        #pragma unroll
        for (int mf = 0; mf < 4; mf++)
            LDSM_X4(af[0][mf][0], af[0][mf][1], af[0][mf][2], af[0][mf][3],
                    Ab + mf * (16 * RB));
        #pragma unroll
        for (int p = 0; p < 2; p++)
            LDSM_X4(bf[0][2 * p][0], bf[0][2 * p][1], bf[0][2 * p + 1][0], bf[0][2 * p + 1][1],
                    Bb + p * (16 * RB));

        #pragma unroll
        for (int kk = 0; kk < 4; kk++) {
            const int cur = kk & 1, nxt = cur ^ 1;
            if (kk < 3) {   // prefetch kk+1 fragments into the alternate buffer
                #pragma unroll
                for (int mf = 0; mf < 4; mf++)
                    LDSM_X4(af[nxt][mf][0], af[nxt][mf][1], af[nxt][mf][2], af[nxt][mf][3],
                            Ab + mf * (16 * RB) + (kk + 1) * 32);
                #pragma unroll
                for (int p = 0; p < 2; p++)
                    LDSM_X4(bf[nxt][2 * p][0], bf[nxt][2 * p][1],
                            bf[nxt][2 * p + 1][0], bf[nxt][2 * p + 1][1],
                            Bb + p * (16 * RB) + (kk + 1) * 32);
            }
            #pragma unroll
            for (int mf = 0; mf < 4; mf++)
                #pragma unroll
                for (int nf = 0; nf < 4; nf++) {
                    float* c = acc + (mf * 4 + nf) * 4;
                    asm volatile(
                        "mma.sync.aligned.m16n8k16.row.col.f32.f16.f16.f32 "
                        "{%0,%1,%2,%3}, {%4,%5,%6,%7}, {%8,%9}, {%0,%1,%2,%3};"
                        : "+f"(c[0]), "+f"(c[1]), "+f"(c[2]), "+f"(c[3])
                        : "r"(af[cur][mf][0]), "r"(af[cur][mf][1]),
                          "r"(af[cur][mf][2]), "r"(af[cur][mf][3]),
                          "r"(bf[cur][nf][0]), "r"(bf[cur][nf][1]));
                }
        }
    }
}

// ---------------- GroupNorm ----------------
#define GSZ (CH / NG * HW)
__global__ __launch_bounds__(256) void gn_stats(const float* __restrict__ x) {
    int bg = blockIdx.x;
    const float4* p = (const float4*)(x + (size_t)bg * GSZ);
    float s = 0.f, sq = 0.f;
    for (int i = threadIdx.x; i < GSZ / 4; i += 256) {
        float4 v = p[i];
        s  += v.x + v.y + v.z + v.w;
        sq += v.x * v.x + v.y * v.y + v.z * v.z + v.w * v.w;
    }
    __shared__ float ss[8], sr[8];
    #pragma unroll
    for (int o = 16; o; o >>= 1) { s += __shfl_down_sync(~0u, s, o); sq += __shfl_down_sync(~0u, sq, o); }
    int w = threadIdx.x >> 5, l = threadIdx.x & 31;
    if (l == 0) { ss[w] = s; sr[w] = sq; }
    __syncthreads();
    if (w == 0) {
        s  = (l < 8) ? ss[l] : 0.f;
        sq = (l < 8) ? sr[l] : 0.f;
        #pragma unroll
        for (int o = 4; o; o >>= 1) { s += __shfl_down_sync(~0u, s, o); sq += __shfl_down_sync(~0u, sq, o); }
        if (l == 0) {
            float mu = s * (1.f / GSZ);
            float va = sq * (1.f / GSZ) - mu * mu;
            g_mean[bg] = mu;
            g_rstd[bg] = rsqrtf(va + EPS);
        }
    }
}

__global__ __launch_bounds__(256) void gn_apply_T(const float* __restrict__ x,
                                                  const float* __restrict__ gw,
                                                  const float* __restrict__ gb) {
    __shared__ float t[32][33];
    int b = blockIdx.z, c0 = blockIdx.y * 32, n0 = blockIdx.x * 32;
    int tx = threadIdx.x, ty = threadIdx.y;   // 32 x 8
    #pragma unroll
    for (int i = 0; i < 4; i++) {
        int c  = c0 + ty + i * 8;
        int bg = b * NG + (c >> 4);
        float r = g_rstd[bg];
        float w = gw[c] * r;
        float bb = gb[c] - g_mean[bg] * w;
        t[ty + i * 8][tx] = x[((size_t)b * CH + c) * HW + n0 + tx] * w + bb;
    }
    __syncthreads();
    #pragma unroll
    for (int i = 0; i < 4; i++) {
        int n = n0 + ty + i * 8;
        g_hnT[((size_t)b * HW + n) * CH + c0 + tx] = __float2half_rn(t[tx][ty + i * 8]);
    }
}

__global__ __launch_bounds__(256) void conv_w(const float* __restrict__ qw,
                                              const float* __restrict__ pw) {
    int i = blockIdx.x * 256 + threadIdx.x;
    const int NQ = 3 * CH * CH;
    float v = (i < NQ) ? qw[i] : pw[i - NQ];
    g_w16[i] = __float2half_rn(v);
}

// ---------------- QKV: D[o][n] = qkv_w x hn ----------------
__global__ __launch_bounds__(256, 2) void k_qkv(const float* __restrict__ qkv_b) {
    extern __shared__ char sm[];
    int n0 = blockIdx.x * 128, o0 = blockIdx.y * 128, b = blockIdx.z;
    float acc[64];
    hgemm_block(g_w16 + (size_t)o0 * CH, CH,
                g_hnT + ((size_t)b * HW + n0) * CH, CH, CH, sm, acc);

    int tid = threadIdx.x, lane = tid & 31, w = tid >> 5;
    int wm = w & 1, wn = w >> 1, g = lane >> 2, ti = lane & 3;

    if (o0 < 1024) {   // q,k: coalesced direct [o][n] stores
        #pragma unroll
        for (int mf = 0; mf < 4; mf++) {
            int oa = o0 + wm * 64 + mf * 16 + g;
            float ba = qkv_b[oa], bb = qkv_b[oa + 8];
            #pragma unroll
            for (int nf = 0; nf < 4; nf++) {
                int n = n0 + wn * 32 + nf * 8 + ti * 2;
                float* c = acc + (mf * 4 + nf) * 4;
                *(__half2*)(g_qk + ((size_t)(b * 1024 + oa)) * HW + n) =
                    __floats2half2_rn(c[0] + ba, c[1] + ba);
                *(__half2*)(g_qk + ((size_t)(b * 1024 + oa + 8)) * HW + n) =
                    __floats2half2_rn(c[2] + bb, c[3] + bb);
            }
        }
    } else {           // v: transpose via SMEM -> vT[n][e]
        __syncthreads();
        __half* Ts = (__half*)sm;   // [128 n][136]
        #pragma unroll
        for (int mf = 0; mf < 4; mf++) {
            int ol = wm * 64 + mf * 16 + g;
            float ba = qkv_b[o0 + ol], bb = qkv_b[o0 + ol + 8];
            #pragma unroll
            for (int nf = 0; nf < 4; nf++) {
                int nl = wn * 32 + nf * 8 + ti * 2;
                float* c = acc + (mf * 4 + nf) * 4;
                Ts[(nl    ) * 136 + ol    ] = __float2half_rn(c[0] + ba);
                Ts[(nl + 1) * 136 + ol    ] = __float2half_rn(c[1] + ba);
                Ts[(nl    ) * 136 + ol + 8] = __float2half_rn(c[2] + bb);
                Ts[(nl + 1) * 136 + ol + 8] = __float2half_rn(c[3] + bb);
            }
        }
        __syncthreads();
        int r = tid >> 1, part = tid & 1;
        uint4* dst = (uint4*)(g_vT + ((size_t)b * HW + n0 + r) * CH + (o0 - 1024) + part * 64);
        const uint4* src = (const uint4*)(Ts + r * 136 + part * 64);
        #pragma unroll
        for (int j = 0; j < 8; j++) dst[j] = src[j];
    }
}

// ---------------- QK^T split-K partials: Sp[bh][chunk] = q_chunk x k_chunk^T ----------------
__global__ __launch_bounds__(256, 2) void qk_part() {
    extern __shared__ char sm[];
    int chunk = blockIdx.x, bh = blockIdx.y, b = bh >> 2, h = bh & 3;
    const __half* A = g_qk + ((size_t)(b * 1024 + h * DH)) * HW + chunk * (HW / NCHUNK);
    const __half* B = g_qk + ((size_t)(b * 1024 + 512 + h * DH)) * HW + chunk * (HW / NCHUNK);
    float acc[64];
    hgemm_block(A, HW, B, HW, HW / NCHUNK, sm, acc);

    float* Sp = g_Sp + ((size_t)bh * NCHUNK + chunk) * DH * DH;
    int lane = threadIdx.x & 31, w = threadIdx.x >> 5;
    int wm = w & 1, wn = w >> 1, g = lane >> 2, ti = lane & 3;
    #pragma unroll
    for (int mf = 0; mf < 4; mf++) {
        int ml = wm * 64 + mf * 16 + g;
        #pragma unroll
        for (int nf = 0; nf < 4; nf++) {
            int nl = wn * 32 + nf * 8 + ti * 2;
            float* c = acc + (mf * 4 + nf) * 4;
            *(float2*)(Sp + (size_t)ml * DH + nl)       = make_float2(c[0], c[1]);
            *(float2*)(Sp + (size_t)(ml + 8) * DH + nl) = make_float2(c[2], c[3]);
        }
    }
}

// ---------------- reduce partials + scale + softmax -> g_at fp16 ----------------
__global__ __launch_bounds__(128) void k_softmax() {
    int row = blockIdx.x, bh = blockIdx.y, t = threadIdx.x;
    const float* Sp = g_Sp + (size_t)bh * NCHUNK * DH * DH + (size_t)row * DH + t;
    float v = 0.f;
    #pragma unroll
    for (int c = 0; c < NCHUNK; c++) v += Sp[(size_t)c * DH * DH];
    v *= 0.08838834764831845f;   // 128^-0.5

    __shared__ float red[4];
    int w = t >> 5, l = t & 31;
    float m = v;
    #pragma unroll
    for (int o = 16; o; o >>= 1) m = fmaxf(m, __shfl_xor_sync(~0u, m, o));
    if (l == 0) red[w] = m;
    __syncthreads();
    m = fmaxf(fmaxf(red[0], red[1]), fmaxf(red[2], red[3]));
    __syncthreads();
    float e = __expf(v - m), su = e;
    #pragma unroll
    for (int o = 16; o; o >>= 1) su += __shfl_xor_sync(~0u, su, o);
    if (l == 0) red[w] = su;
    __syncthreads();
    su = red[0] + red[1] + red[2] + red[3];
    g_at[((size_t)bh * DH + row) * DH + t] = __float2half_rn(e / su);
}

// ---------------- AV: ao[d][n] -> aoT[n][c] ----------------
__global__ __launch_bounds__(256, 2) void k_av() {
    extern __shared__ char sm[];
    int n0 = blockIdx.x * 128, bh = blockIdx.z, b = bh >> 2, h = bh & 3;
    float acc[64];
    hgemm_block(g_at + (size_t)bh * DH * DH, DH,
                g_vT + ((size_t)b * HW + n0) * CH + h * DH, CH, DH, sm, acc);
    __syncthreads();

    __half* Ts = (__half*)sm;   // [128 n][136]
    int tid = threadIdx.x, lane = tid & 31, w = tid >> 5;
    int wm = w & 1, wn = w >> 1, g = lane >> 2, ti = lane & 3;
    #pragma unroll
    for (int mf = 0; mf < 4; mf++) {
        int dl = wm * 64 + mf * 16 + g;
        #pragma unroll
        for (int nf = 0; nf < 4; nf++) {
            int nl = wn * 32 + nf * 8 + ti * 2;
            float* c = acc + (mf * 4 + nf) * 4;
            Ts[(nl    ) * 136 + dl    ] = __float2half_rn(c[0]);
            Ts[(nl + 1) * 136 + dl    ] = __float2half_rn(c[1]);
            Ts[(nl    ) * 136 + dl + 8] = __float2half_rn(c[2]);
            Ts[(nl + 1) * 136 + dl + 8] = __float2half_rn(c[3]);
        }
    }
    __syncthreads();
    int r = tid >> 1, part = tid & 1;
    uint4* dst = (uint4*)(g_aoT + ((size_t)b * HW + n0 + r) * CH + h * DH + part * 64);
    const uint4* src = (const uint4*)(Ts + r * 136 + part * 64);
    #pragma unroll
    for (int j = 0; j < 8; j++) dst[j] = src[j];
}

// ---------------- proj + bias + residual ----------------
__global__ __launch_bounds__(256, 2) void k_proj(const float* __restrict__ proj_b,
                                                 const float* __restrict__ x,
                                                 float* __restrict__ out) {
    extern __shared__ char sm[];
    int n0 = blockIdx.x * 128, o0 = blockIdx.y * 128, b = blockIdx.z;
    float acc[64];
    hgemm_block(g_w16 + (size_t)3 * CH * CH + (size_t)o0 * CH, CH,
                g_aoT + ((size_t)b * HW + n0) * CH, CH, CH, sm, acc);

    int tid = threadIdx.x, lane = tid & 31, w = tid >> 5;
    int wm = w & 1, wn = w >> 1, g = lane >> 2, ti = lane & 3;
    #pragma unroll
    for (int mf = 0; mf < 4; mf++) {
        int oa = o0 + wm * 64 + mf * 16 + g;
        float ba = proj_b[oa], bb = proj_b[oa + 8];
        #pragma unroll
        for (int nf = 0; nf < 4; nf++) {
            int n = n0 + wn * 32 + nf * 8 + ti * 2;
            float* c = acc + (mf * 4 + nf) * 4;
            size_t o1 = ((size_t)b * CH + oa) * HW + n;
            size_t o2 = ((size_t)b * CH + oa + 8) * HW + n;
            float2 r1 = *(const float2*)(x + o1);
            float2 r2 = *(const float2*)(x + o2);
            *(float2*)(out + o1) = make_float2(c[0] + ba + r1.x, c[1] + ba + r1.y);
            *(float2*)(out + o2) = make_float2(c[2] + bb + r2.x, c[3] + bb + r2.y);
        }
    }
}

// ---------------- host ----------------
#define SMEM_G (2 * 128 * RB * 3)   // 110592/CTA; x2 CTAs = 216KB/SM

extern "C" void kernel_launch(void* const* d_in, const int* in_sizes, int n_in,
                              void* d_out, int out_size) {
    const float* x      = (const float*)d_in[0];
    const float* gn_w   = (const float*)d_in[1];
    const float* gn_b   = (const float*)d_in[2];
    const float* qkv_w  = (const float*)d_in[3];
    const float* qkv_b  = (const float*)d_in[4];
    const float* proj_w = (const float*)d_in[5];
    const float* proj_b = (const float*)d_in[6];
    float* out = (float*)d_out;

    cudaFuncSetAttribute(k_qkv,   cudaFuncAttributeMaxDynamicSharedMemorySize, SMEM_G);
    cudaFuncSetAttribute(qk_part, cudaFuncAttributeMaxDynamicSharedMemorySize, SMEM_G);
    cudaFuncSetAttribute(k_av,    cudaFuncAttributeMaxDynamicSharedMemorySize, SMEM_G);
    cudaFuncSetAttribute(k_proj,  cudaFuncAttributeMaxDynamicSharedMemorySize, SMEM_G);

    gn_stats<<<BATCH * NG, 256>>>(x);
    gn_apply_T<<<dim3(HW / 32, CH / 32, BATCH), dim3(32, 8)>>>(x, gn_w, gn_b);
    conv_w<<<(4 * CH * CH) / 256, 256>>>(qkv_w, proj_w);

    k_qkv  <<<dim3(HW / 128, 12, BATCH), 256, SMEM_G>>>(qkv_b);
    qk_part<<<dim3(NCHUNK, BATCH * HEADS), 256, SMEM_G>>>();
    k_softmax<<<dim3(DH, BATCH * HEADS), 128>>>();
    k_av   <<<dim3(HW / 128, 1, BATCH * HEADS), 256, SMEM_G>>>();
    k_proj <<<dim3(HW / 128, CH / 128, BATCH), 256, SMEM_G>>>(proj_b, x, out);

    (void)in_sizes; (void)n_in; (void)out_size;
}